// round 12
// baseline (speedup 1.0000x reference)
#include <cuda_runtime.h>
#include <cuda_bf16.h>
#include <math.h>

// Problem constants
#define BATCH  8
#define T_DIM  1024
#define I_DIM  576
#define C_DIM  1024
#define N_HEAD 16
#define HD     64

// ---------------------------------------------------------------------------
// Scratch: split-bf16 planes. uint2 = (bf16x2 hi, bf16x2 lo), pairs along last
// dim: word w of a row covers elements (2w, 2w+1).
// ---------------------------------------------------------------------------
__device__ uint2 g_xs  [BATCH * T_DIM * C_DIM / 2];
__device__ uint2 g_es  [BATCH * I_DIM * C_DIM / 2];
__device__ uint2 g_wqs [C_DIM * C_DIM / 2];
__device__ uint2 g_wkvs[2 * C_DIM * C_DIM / 2];
__device__ uint2 g_wos [C_DIM * C_DIM / 2];
__device__ uint2 g_qs  [BATCH * T_DIM * C_DIM / 2];
__device__ uint2 g_kvs [BATCH * I_DIM * 2 * C_DIM / 2];
__device__ uint2 g_ys  [BATCH * T_DIM * C_DIM / 2];

// ---------------------------------------------------------------------------
// helpers
// ---------------------------------------------------------------------------
__device__ __forceinline__ unsigned pack_bf2(float x, float y) {
    __nv_bfloat162 t = __floats2bfloat162_rn(x, y);
    return *reinterpret_cast<unsigned*>(&t);
}
__device__ __forceinline__ uint2 splitw(float x, float y) {
    float hx = __bfloat162float(__float2bfloat16(x));
    float hy = __bfloat162float(__float2bfloat16(y));
    return make_uint2(pack_bf2(hx, hy), pack_bf2(x - hx, y - hy));
}
__device__ __forceinline__ unsigned prmt(unsigned a, unsigned b, unsigned s) {
    unsigned d;
    asm("prmt.b32 %0,%1,%2,%3;" : "=r"(d) : "r"(a), "r"(b), "r"(s));
    return d;
}
__device__ __forceinline__ void mma_bf16(float* c,
    unsigned a0, unsigned a1, unsigned a2, unsigned a3,
    unsigned b0, unsigned b1)
{
    asm volatile(
        "mma.sync.aligned.m16n8k16.row.col.f32.bf16.bf16.f32 "
        "{%0,%1,%2,%3},{%4,%5,%6,%7},{%8,%9},{%0,%1,%2,%3};\n"
        : "+f"(c[0]), "+f"(c[1]), "+f"(c[2]), "+f"(c[3])
        : "r"(a0), "r"(a1), "r"(a2), "r"(a3), "r"(b0), "r"(b1));
}
__device__ __forceinline__ void mma_split(float* c, const uint2 a[4], const uint2 b[2]) {
    mma_bf16(c, a[0].x, a[1].x, a[2].x, a[3].x, b[0].x, b[1].x);
    mma_bf16(c, a[0].y, a[1].y, a[2].y, a[3].y, b[0].x, b[1].x);
    mma_bf16(c, a[0].x, a[1].x, a[2].x, a[3].x, b[0].y, b[1].y);
}

// ---------------------------------------------------------------------------
// conversion: fp32 tensor -> split planes
// ---------------------------------------------------------------------------
__global__ __launch_bounds__(256) void convert_split(
    const float2* __restrict__ src, uint2* __restrict__ dst, int n)
{
    int i = blockIdx.x * 256 + threadIdx.x;
    if (i < n) { float2 v = src[i]; dst[i] = splitw(v.x, v.y); }
}

// ---------------------------------------------------------------------------
// GEMM NT on split planes: C[M,N] = A[M,K] B[N,K]^T + bias
// 512 threads, 16 warps (4m x 4n), warp tile 32x32. Block 128x128.
// Stage = 16 words (k32), double-buffered dynamic smem.
// Threads 0..255 load A, 256..511 load B (64B contiguous per thread).
// ---------------------------------------------------------------------------
#define MS2 132
__device__ __forceinline__ int sidx(int kw, int m) {
    return kw * MS2 + (m ^ ((kw & 3) << 3));
}
#define STG16 (16 * MS2)                       // uint2 per matrix per buffer
#define GEMM_SMEM (4 * STG16 * (int)sizeof(uint2))   // 67584 B

__device__ __forceinline__ void store_stage(uint2* d, int jb, int lr,
                                            const uint4 pf[4]) {
#pragma unroll
    for (int j = 0; j < 4; j++) {
        d[sidx(jb + 2 * j,     lr)] = make_uint2(pf[j].x, pf[j].y);
        d[sidx(jb + 2 * j + 1, lr)] = make_uint2(pf[j].z, pf[j].w);
    }
}

template<bool SPLIT_OUT>
__global__ __launch_bounds__(512) void gemm_split(
    const uint2* __restrict__ AS, const uint2* __restrict__ BS,
    const float* __restrict__ bias, float* __restrict__ Cf,
    uint2* __restrict__ Cs, int M, int N, int KW)
{
    extern __shared__ uint2 sm[];   // A0 A1 B0 B1, each STG16

    const int tid  = threadIdx.x;
    const int wid  = tid >> 5;
    const int lane = tid & 31;
    const int g    = lane >> 2;
    const int tig  = lane & 3;
    const int t8   = tig << 3;
    const int wm   = (wid >> 2) * 32;
    const int wn   = (wid & 3) * 32;
    const int m0   = blockIdx.y * 128;
    const int n0   = blockIdx.x * 128;

    // loader role: first 256 threads -> A, last 256 -> B
    const int  lt    = tid & 255;
    const int  lr    = lt >> 1;          // 0..127
    const int  jb    = (lt & 1) * 8;     // word 0 or 8
    const bool loadB = tid >= 256;
    const uint2* Gp = (loadB ? BS + (size_t)(n0 + lr) * KW
                             : AS + (size_t)(m0 + lr) * KW) + jb;
    uint2* sDst = sm + (loadB ? 2 * STG16 : 0);

    float acc[2][4][4];
#pragma unroll
    for (int mt = 0; mt < 2; mt++)
#pragma unroll
        for (int nt = 0; nt < 4; nt++)
#pragma unroll
            for (int r = 0; r < 4; r++) acc[mt][nt][r] = 0.f;

    const int NS = KW >> 4;     // stages of 16 words (k32)
    uint4 pf[4];

    // prologue: stage 0
    {
        const uint4* p = (const uint4*)Gp;
        pf[0] = p[0]; pf[1] = p[1]; pf[2] = p[2]; pf[3] = p[3];
        store_stage(sDst, jb, lr, pf);
    }
    __syncthreads();

    for (int s = 0; s < NS; s++) {
        if (s + 1 < NS) {
            const uint4* p = (const uint4*)(Gp + (size_t)(s + 1) * 16);
            pf[0] = p[0]; pf[1] = p[1]; pf[2] = p[2]; pf[3] = p[3];
        }

        const uint2* sa = sm + (s & 1) * STG16;
        const uint2* sb = sm + 2 * STG16 + (s & 1) * STG16;

#pragma unroll
        for (int ks = 0; ks < 2; ks++) {
            const int kwa = 8 * ks + tig;
            uint2 af[2][4];
#pragma unroll
            for (int mt = 0; mt < 2; mt++) {
                const int r = wm + 16 * mt + g;
                af[mt][0] = sa[kwa * MS2 + (r ^ t8)];
                af[mt][1] = sa[kwa * MS2 + ((r + 8) ^ t8)];
                af[mt][2] = sa[(kwa + 4) * MS2 + (r ^ t8)];
                af[mt][3] = sa[(kwa + 4) * MS2 + ((r + 8) ^ t8)];
            }
            uint2 bf[4][2];
#pragma unroll
            for (int nt = 0; nt < 4; nt++) {
                const int c = wn + 8 * nt + g;
                bf[nt][0] = sb[kwa * MS2 + (c ^ t8)];
                bf[nt][1] = sb[(kwa + 4) * MS2 + (c ^ t8)];
            }
#pragma unroll
            for (int mt = 0; mt < 2; mt++)
#pragma unroll
                for (int nt = 0; nt < 4; nt++)
                    mma_split(acc[mt][nt], af[mt], bf[nt]);
        }

        if (s + 1 < NS)
            store_stage(sDst + ((s + 1) & 1) * STG16, jb, lr, pf);
        __syncthreads();
    }

    // epilogue
#pragma unroll
    for (int mt = 0; mt < 2; mt++) {
        const int r0 = m0 + wm + 16 * mt + g;
#pragma unroll
        for (int nt = 0; nt < 4; nt++) {
            const int cb = n0 + wn + 8 * nt + 2 * tig;
            const float v0 = bias[cb], v1 = bias[cb + 1];
            if (SPLIT_OUT) {
                Cs[(size_t)r0 * (N >> 1) + (cb >> 1)] =
                    splitw(acc[mt][nt][0] + v0, acc[mt][nt][1] + v1);
                Cs[(size_t)(r0 + 8) * (N >> 1) + (cb >> 1)] =
                    splitw(acc[mt][nt][2] + v0, acc[mt][nt][3] + v1);
            } else {
                *(float2*)(Cf + (size_t)r0 * N + cb) =
                    make_float2(acc[mt][nt][0] + v0, acc[mt][nt][1] + v1);
                *(float2*)(Cf + (size_t)(r0 + 8) * N + cb) =
                    make_float2(acc[mt][nt][2] + v0, acc[mt][nt][3] + v1);
            }
        }
    }
}

// ---------------------------------------------------------------------------
// Flash attention via split-mma (R8 structure; softmax in log2 domain)
// ---------------------------------------------------------------------------
#define AQ2 136
#define AK2 68
#define ATTN_BYTES ((32 * AQ2 + 2 * 32 * AK2) * 8)
#define SCALE_L2E 0.1803368801111204f   // 0.125 * log2(e)

__global__ __launch_bounds__(256) void attn_flash(
    const uint2* __restrict__ qs, const uint2* __restrict__ kvs,
    uint2* __restrict__ ys)
{
    extern __shared__ uint2 smem2[];
    uint2* sQ = smem2;
    uint2* sK = sQ + 32 * AQ2;
    uint2* sV = sK + 32 * AK2;

    const int tid  = threadIdx.x;
    const int wid  = tid >> 5;
    const int lane = tid & 31;
    const int g    = lane >> 2;
    const int tig  = lane & 3;
    const int t8   = tig << 3;
    const int wm   = wid * 16;

    const int b  = blockIdx.z;
    const int h  = blockIdx.y;
    const int t0 = blockIdx.x * 128;

#pragma unroll
    for (int w = 0; w < 16; w++) {
        int idx = tid + 256 * w;
        int r = idx >> 5, dw = idx & 31;
        sQ[dw * AQ2 + (r ^ ((dw & 3) << 3))] =
            qs[(size_t)(b * T_DIM + t0 + r) * 512 + h * 32 + dw];
    }

    float yacc[8][4];
#pragma unroll
    for (int dt = 0; dt < 8; dt++)
#pragma unroll
        for (int r = 0; r < 4; r++) yacc[dt][r] = 0.f;
    float m0r = -1e30f, m1r = -1e30f;
    float l0r = 0.f, l1r = 0.f;

    __syncthreads();

    for (int c = 0; c < 9; c++) {
        const int i0 = c * 64;
#pragma unroll
        for (int w = 0; w < 8; w++) {
            int idx = tid + 256 * w;
            int r = idx >> 5, dw = idx & 31;
            sK[dw * AK2 + (r ^ ((dw & 3) << 3))] =
                kvs[(size_t)(b * I_DIM + i0 + r) * 1024 + h * 32 + dw];
        }
        __syncthreads();

        float sacc[8][4];
#pragma unroll
        for (int nt = 0; nt < 8; nt++)
#pragma unroll
            for (int r = 0; r < 4; r++) sacc[nt][r] = 0.f;

#pragma unroll
        for (int ks = 0; ks < 4; ks++) {
            const int kwa = 8 * ks + tig;
            uint2 af[4];
            af[0] = sQ[kwa * AQ2 + ((wm + g) ^ t8)];
            af[1] = sQ[kwa * AQ2 + ((wm + g + 8) ^ t8)];
            af[2] = sQ[(kwa + 4) * AQ2 + ((wm + g) ^ t8)];
            af[3] = sQ[(kwa + 4) * AQ2 + ((wm + g + 8) ^ t8)];
#pragma unroll
            for (int nt = 0; nt < 8; nt++) {
                const int cc = 8 * nt + g;
                uint2 bf2[2];
                bf2[0] = sK[kwa * AK2 + (cc ^ t8)];
                bf2[1] = sK[(kwa + 4) * AK2 + (cc ^ t8)];
                mma_split(sacc[nt], af, bf2);
            }
        }

        // scores scaled into log2 domain
        float cm0 = -1e30f, cm1 = -1e30f;
#pragma unroll
        for (int nt = 0; nt < 8; nt++) {
            sacc[nt][0] *= SCALE_L2E; sacc[nt][1] *= SCALE_L2E;
            sacc[nt][2] *= SCALE_L2E; sacc[nt][3] *= SCALE_L2E;
            cm0 = fmaxf(cm0, fmaxf(sacc[nt][0], sacc[nt][1]));
            cm1 = fmaxf(cm1, fmaxf(sacc[nt][2], sacc[nt][3]));
        }
        cm0 = fmaxf(cm0, __shfl_xor_sync(0xffffffffu, cm0, 1));
        cm0 = fmaxf(cm0, __shfl_xor_sync(0xffffffffu, cm0, 2));
        cm1 = fmaxf(cm1, __shfl_xor_sync(0xffffffffu, cm1, 1));
        cm1 = fmaxf(cm1, __shfl_xor_sync(0xffffffffu, cm1, 2));

        const float mn0 = fmaxf(m0r, cm0);
        const float mn1 = fmaxf(m1r, cm1);
        const float f0 = exp2f(m0r - mn0);
        const float f1 = exp2f(m1r - mn1);

        float cs0 = 0.f, cs1 = 0.f;
#pragma unroll
        for (int nt = 0; nt < 8; nt++) {
            sacc[nt][0] = exp2f(sacc[nt][0] - mn0);
            sacc[nt][1] = exp2f(sacc[nt][1] - mn0);
            sacc[nt][2] = exp2f(sacc[nt][2] - mn1);
            sacc[nt][3] = exp2f(sacc[nt][3] - mn1);
            cs0 += sacc[nt][0] + sacc[nt][1];
            cs1 += sacc[nt][2] + sacc[nt][3];
        }
        cs0 += __shfl_xor_sync(0xffffffffu, cs0, 1);
        cs0 += __shfl_xor_sync(0xffffffffu, cs0, 2);
        cs1 += __shfl_xor_sync(0xffffffffu, cs1, 1);
        cs1 += __shfl_xor_sync(0xffffffffu, cs1, 2);

        l0r = l0r * f0 + cs0;  m0r = mn0;
        l1r = l1r * f1 + cs1;  m1r = mn1;
#pragma unroll
        for (int dt = 0; dt < 8; dt++) {
            yacc[dt][0] *= f0; yacc[dt][1] *= f0;
            yacc[dt][2] *= f1; yacc[dt][3] *= f1;
        }

#pragma unroll
        for (int p = 0; p < 4; p++) {
            int P = tid + 256 * p;
            int iw = P >> 5, dv = P & 31;
            uint2 r0 = kvs[(size_t)(b * I_DIM + i0 + 2 * iw) * 1024 + 512 + h * 32 + dv];
            uint2 r1 = kvs[(size_t)(b * I_DIM + i0 + 2 * iw + 1) * 1024 + 512 + h * 32 + dv];
            sV[iw * AK2 + ((2 * dv) ^ ((iw & 3) << 3))] =
                make_uint2(prmt(r0.x, r1.x, 0x5410), prmt(r0.y, r1.y, 0x5410));
            sV[iw * AK2 + ((2 * dv + 1) ^ ((iw & 3) << 3))] =
                make_uint2(prmt(r0.x, r1.x, 0x7632), prmt(r0.y, r1.y, 0x7632));
        }
        __syncthreads();

#pragma unroll
        for (int ks = 0; ks < 4; ks++) {
            uint2 a[4];
            a[0] = splitw(sacc[2 * ks][0],     sacc[2 * ks][1]);
            a[1] = splitw(sacc[2 * ks][2],     sacc[2 * ks][3]);
            a[2] = splitw(sacc[2 * ks + 1][0], sacc[2 * ks + 1][1]);
            a[3] = splitw(sacc[2 * ks + 1][2], sacc[2 * ks + 1][3]);
            const int kwa = 8 * ks + tig;
#pragma unroll
            for (int dt = 0; dt < 8; dt++) {
                const int cc = 8 * dt + g;
                uint2 bf2[2];
                bf2[0] = sV[kwa * AK2 + (cc ^ t8)];
                bf2[1] = sV[(kwa + 4) * AK2 + (cc ^ t8)];
                mma_split(yacc[dt], a, bf2);
            }
        }
        __syncthreads();
    }

    const float inv0 = 1.0f / l0r;
    const float inv1 = 1.0f / l1r;
    const size_t r0 = (size_t)(b * T_DIM + t0 + wm + g);
#pragma unroll
    for (int dt = 0; dt < 8; dt++) {
        const int col = 8 * dt + 2 * tig;
        const int cw  = h * 32 + (col >> 1);
        ys[r0 * 512 + cw]       = splitw(yacc[dt][0] * inv0, yacc[dt][1] * inv0);
        ys[(r0 + 8) * 512 + cw] = splitw(yacc[dt][2] * inv1, yacc[dt][3] * inv1);
    }
}

// ---------------------------------------------------------------------------
// Launch
// ---------------------------------------------------------------------------
extern "C" void kernel_launch(void* const* d_in, const int* in_sizes, int n_in,
                              void* d_out, int out_size)
{
    const float* x   = (const float*)d_in[0];
    const float* enc = (const float*)d_in[1];
    const float* Wq  = (const float*)d_in[2];
    const float* bq  = (const float*)d_in[3];
    const float* Wkv = (const float*)d_in[4];
    const float* bkv = (const float*)d_in[5];
    const float* Wo  = (const float*)d_in[6];
    const float* bo  = (const float*)d_in[7];
    float* out = (float*)d_out;

    uint2 *xs, *es, *wqs, *wkvs, *wos, *qsp, *kvsp, *ysp;
    cudaGetSymbolAddress((void**)&xs,   g_xs);
    cudaGetSymbolAddress((void**)&es,   g_es);
    cudaGetSymbolAddress((void**)&wqs,  g_wqs);
    cudaGetSymbolAddress((void**)&wkvs, g_wkvs);
    cudaGetSymbolAddress((void**)&wos,  g_wos);
    cudaGetSymbolAddress((void**)&qsp,  g_qs);
    cudaGetSymbolAddress((void**)&kvsp, g_kvs);
    cudaGetSymbolAddress((void**)&ysp,  g_ys);

    cudaFuncSetAttribute(gemm_split<true>,
                         cudaFuncAttributeMaxDynamicSharedMemorySize, GEMM_SMEM);
    cudaFuncSetAttribute(gemm_split<false>,
                         cudaFuncAttributeMaxDynamicSharedMemorySize, GEMM_SMEM);
    cudaFuncSetAttribute(attn_flash,
                         cudaFuncAttributeMaxDynamicSharedMemorySize, ATTN_BYTES);

    // conversions (fp32 -> split planes)
    {
        int n;
        n = BATCH * T_DIM * C_DIM / 2;
        convert_split<<<(n + 255) / 256, 256>>>((const float2*)x, xs, n);
        n = BATCH * I_DIM * C_DIM / 2;
        convert_split<<<(n + 255) / 256, 256>>>((const float2*)enc, es, n);
        n = C_DIM * C_DIM / 2;
        convert_split<<<(n + 255) / 256, 256>>>((const float2*)Wq, wqs, n);
        n = 2 * C_DIM * C_DIM / 2;
        convert_split<<<(n + 255) / 256, 256>>>((const float2*)Wkv, wkvs, n);
        n = C_DIM * C_DIM / 2;
        convert_split<<<(n + 255) / 256, 256>>>((const float2*)Wo, wos, n);
    }

    // Q = x Wq^T + bq  -> split q
    gemm_split<true><<<dim3(C_DIM / 128, BATCH * T_DIM / 128), 512, GEMM_SMEM>>>(
        xs, wqs, bq, nullptr, qsp, BATCH * T_DIM, C_DIM, C_DIM / 2);

    // KV = enc Wkv^T + bkv -> split kv
    gemm_split<true><<<dim3(2 * C_DIM / 128, BATCH * I_DIM / 128), 512, GEMM_SMEM>>>(
        es, wkvs, bkv, nullptr, kvsp, BATCH * I_DIM, 2 * C_DIM, C_DIM / 2);

    // flash attention -> split y
    attn_flash<<<dim3(T_DIM / 128, N_HEAD, BATCH), 256, ATTN_BYTES>>>(
        qsp, kvsp, ysp);

    // out = y Wo^T + bo  (fp32)
    gemm_split<false><<<dim3(C_DIM / 128, BATCH * T_DIM / 128), 512, GEMM_SMEM>>>(
        ysp, wos, bo, out, nullptr, BATCH * T_DIM, C_DIM, C_DIM / 2);
}

// round 13
// speedup vs baseline: 1.2027x; 1.2027x over previous
#include <cuda_runtime.h>
#include <cuda_bf16.h>
#include <cuda_fp16.h>
#include <math.h>

// Problem constants
#define BATCH  8
#define T_DIM  1024
#define I_DIM  576
#define C_DIM  1024
#define N_HEAD 16
#define HD     64

// ---------------------------------------------------------------------------
// Scratch: split-fp16 planes. uint2 = (f16x2 hi, f16x2 lo), pairs along last
// dim: word w of a row covers elements (2w, 2w+1).
// ---------------------------------------------------------------------------
__device__ uint2 g_xs  [BATCH * T_DIM * C_DIM / 2];
__device__ uint2 g_es  [BATCH * I_DIM * C_DIM / 2];
__device__ uint2 g_wqs [C_DIM * C_DIM / 2];
__device__ uint2 g_wkvs[2 * C_DIM * C_DIM / 2];
__device__ uint2 g_wos [C_DIM * C_DIM / 2];
__device__ uint2 g_qs  [BATCH * T_DIM * C_DIM / 2];
__device__ uint2 g_kvs [BATCH * I_DIM * 2 * C_DIM / 2];
__device__ uint2 g_ys  [BATCH * T_DIM * C_DIM / 2];

// ---------------------------------------------------------------------------
// helpers (fp16 2-term split: x = hi + lo, lo captures next 11 bits)
// ---------------------------------------------------------------------------
__device__ __forceinline__ unsigned pack_h2(float x, float y) {
    __half2 t = __floats2half2_rn(x, y);
    return *reinterpret_cast<unsigned*>(&t);
}
__device__ __forceinline__ uint2 splitw(float x, float y) {
    float hx = __half2float(__float2half(x));
    float hy = __half2float(__float2half(y));
    return make_uint2(pack_h2(hx, hy), pack_h2(x - hx, y - hy));
}
__device__ __forceinline__ unsigned prmt(unsigned a, unsigned b, unsigned s) {
    unsigned d;
    asm("prmt.b32 %0,%1,%2,%3;" : "=r"(d) : "r"(a), "r"(b), "r"(s));
    return d;
}
__device__ __forceinline__ void mma_f16(float* c,
    unsigned a0, unsigned a1, unsigned a2, unsigned a3,
    unsigned b0, unsigned b1)
{
    asm volatile(
        "mma.sync.aligned.m16n8k16.row.col.f32.f16.f16.f32 "
        "{%0,%1,%2,%3},{%4,%5,%6,%7},{%8,%9},{%0,%1,%2,%3};\n"
        : "+f"(c[0]), "+f"(c[1]), "+f"(c[2]), "+f"(c[3])
        : "r"(a0), "r"(a1), "r"(a2), "r"(a3), "r"(b0), "r"(b1));
}
// 2-term split product: (ah + al) * bh
__device__ __forceinline__ void mma_split2(float* c, const uint2 a[4],
                                           unsigned b0, unsigned b1) {
    mma_f16(c, a[0].x, a[1].x, a[2].x, a[3].x, b0, b1);
    mma_f16(c, a[0].y, a[1].y, a[2].y, a[3].y, b0, b1);
}

// ---------------------------------------------------------------------------
// conversion: fp32 tensor -> split planes
// ---------------------------------------------------------------------------
__global__ __launch_bounds__(256) void convert_split(
    const float2* __restrict__ src, uint2* __restrict__ dst, int n)
{
    int i = blockIdx.x * 256 + threadIdx.x;
    if (i < n) { float2 v = src[i]; dst[i] = splitw(v.x, v.y); }
}

// ---------------------------------------------------------------------------
// GEMM NT on split planes: C[M,N] = A[M,K] B[N,K]^T + bias
// Block 128x128, stage = k16 (8 words), double-buffered. 8 warps (2m x 4n),
// warp tile 64x32. A smem keeps (hi,lo); B smem stores hi only.
// 2 HMMA per m16n8 tile per k16.
// ---------------------------------------------------------------------------
#define MS2 132
__device__ __forceinline__ int sidx(int kw, int m) {
    return kw * MS2 + (m ^ ((kw & 3) << 3));
}
#define STG (8 * MS2)   // elements per stage buffer (uint2 for A, unsigned for B)

template<bool SPLIT_OUT>
__global__ __launch_bounds__(256) void gemm_split(
    const uint2* __restrict__ AS, const uint2* __restrict__ BS,
    const float* __restrict__ bias, float* __restrict__ Cf,
    uint2* __restrict__ Cs, int M, int N, int KW)
{
    __shared__ uint2    sA[2 * STG];
    __shared__ unsigned sB[2 * STG];

    const int tid  = threadIdx.x;
    const int m0   = blockIdx.y * 128;
    const int n0   = blockIdx.x * 128;
    const int wid  = tid >> 5;
    const int lane = tid & 31;
    const int g    = lane >> 2;
    const int tig  = lane & 3;
    const int t8   = tig << 3;
    const int wm   = (wid >> 2) * 64;
    const int wn   = (wid & 3) * 32;

    const int lr = tid >> 1;          // 0..127
    const int jb = (tid & 1) * 4;     // word offset 0 or 4

    const uint4* Ag = (const uint4*)(AS + (size_t)(m0 + lr) * KW + jb);
    const uint4* Bg = (const uint4*)(BS + (size_t)(n0 + lr) * KW + jb);

    float acc[4][4][4];
#pragma unroll
    for (int i = 0; i < 4; i++)
#pragma unroll
        for (int j = 0; j < 4; j++)
#pragma unroll
            for (int r = 0; r < 4; r++) acc[i][j][r] = 0.f;

    const int NS = KW >> 3;
    uint4 a0, a1, b0, b1;

    // prologue: stage 0
    a0 = Ag[0]; a1 = Ag[1]; b0 = Bg[0]; b1 = Bg[1];
    {
        sA[sidx(jb + 0, lr)] = make_uint2(a0.x, a0.y);
        sA[sidx(jb + 1, lr)] = make_uint2(a0.z, a0.w);
        sA[sidx(jb + 2, lr)] = make_uint2(a1.x, a1.y);
        sA[sidx(jb + 3, lr)] = make_uint2(a1.z, a1.w);
        sB[sidx(jb + 0, lr)] = b0.x;   // hi words only
        sB[sidx(jb + 1, lr)] = b0.z;
        sB[sidx(jb + 2, lr)] = b1.x;
        sB[sidx(jb + 3, lr)] = b1.z;
    }
    __syncthreads();

    for (int s = 0; s < NS; s++) {
        const int cur = s & 1;
        if (s + 1 < NS) {
            const uint4* ap = Ag + (size_t)(s + 1) * 4;
            const uint4* bp = Bg + (size_t)(s + 1) * 4;
            a0 = ap[0]; a1 = ap[1]; b0 = bp[0]; b1 = bp[1];
        }

        const uint2*    sa = sA + cur * STG;
        const unsigned* sb = sB + cur * STG;

        uint2 af[4][4];
#pragma unroll
        for (int mt = 0; mt < 4; mt++) {
            const int r = wm + 16 * mt + g;
            af[mt][0] = sa[tig * MS2 + (r ^ t8)];
            af[mt][1] = sa[tig * MS2 + ((r + 8) ^ t8)];
            af[mt][2] = sa[(tig + 4) * MS2 + (r ^ t8)];
            af[mt][3] = sa[(tig + 4) * MS2 + ((r + 8) ^ t8)];
        }
        unsigned bf[4][2];
#pragma unroll
        for (int nt = 0; nt < 4; nt++) {
            const int c = wn + 8 * nt + g;
            bf[nt][0] = sb[tig * MS2 + (c ^ t8)];
            bf[nt][1] = sb[(tig + 4) * MS2 + (c ^ t8)];
        }
#pragma unroll
        for (int mt = 0; mt < 4; mt++)
#pragma unroll
            for (int nt = 0; nt < 4; nt++)
                mma_split2(acc[mt][nt], af[mt], bf[nt][0], bf[nt][1]);

        if (s + 1 < NS) {
            uint2*    dA = sA + ((s + 1) & 1) * STG;
            unsigned* dB = sB + ((s + 1) & 1) * STG;
            dA[sidx(jb + 0, lr)] = make_uint2(a0.x, a0.y);
            dA[sidx(jb + 1, lr)] = make_uint2(a0.z, a0.w);
            dA[sidx(jb + 2, lr)] = make_uint2(a1.x, a1.y);
            dA[sidx(jb + 3, lr)] = make_uint2(a1.z, a1.w);
            dB[sidx(jb + 0, lr)] = b0.x;
            dB[sidx(jb + 1, lr)] = b0.z;
            dB[sidx(jb + 2, lr)] = b1.x;
            dB[sidx(jb + 3, lr)] = b1.z;
        }
        __syncthreads();
    }

    // epilogue
#pragma unroll
    for (int mt = 0; mt < 4; mt++) {
        const int r0 = m0 + wm + 16 * mt + g;
#pragma unroll
        for (int nt = 0; nt < 4; nt++) {
            const int cb = n0 + wn + 8 * nt + 2 * tig;
            const float v0 = bias[cb], v1 = bias[cb + 1];
            if (SPLIT_OUT) {
                Cs[(size_t)r0 * (N >> 1) + (cb >> 1)] =
                    splitw(acc[mt][nt][0] + v0, acc[mt][nt][1] + v1);
                Cs[(size_t)(r0 + 8) * (N >> 1) + (cb >> 1)] =
                    splitw(acc[mt][nt][2] + v0, acc[mt][nt][3] + v1);
            } else {
                *(float2*)(Cf + (size_t)r0 * N + cb) =
                    make_float2(acc[mt][nt][0] + v0, acc[mt][nt][1] + v1);
                *(float2*)(Cf + (size_t)(r0 + 8) * N + cb) =
                    make_float2(acc[mt][nt][2] + v0, acc[mt][nt][3] + v1);
            }
        }
    }
}

// ---------------------------------------------------------------------------
// Flash attention via 2-term split-mma. Q split (A operand); K/V hi-only (B).
// Block = 128 t-rows x (b,h). 8 warps, warp w owns rows [16w, 16w+16).
// Softmax in log2 domain.
// ---------------------------------------------------------------------------
#define AQ2 136   // sQ stride (uint2)
#define AK2 68    // sK/sV stride (unsigned)
#define ATTN_BYTES (32 * AQ2 * 8 + 2 * 32 * AK2 * 4)   // ~52 KB
#define SCALE_L2E 0.1803368801111204f   // 0.125 * log2(e)

__global__ __launch_bounds__(256) void attn_flash(
    const uint2* __restrict__ qs, const uint2* __restrict__ kvs,
    uint2* __restrict__ ys)
{
    extern __shared__ char smraw[];
    uint2*    sQ = (uint2*)smraw;                          // [32 kw][128 r]
    unsigned* sK = (unsigned*)(smraw + 32 * AQ2 * 8);      // [32 kw][64 r]
    unsigned* sV = sK + 32 * AK2;                          // [32 iw][64 d]

    const int tid  = threadIdx.x;
    const int wid  = tid >> 5;
    const int lane = tid & 31;
    const int g    = lane >> 2;
    const int tig  = lane & 3;
    const int t8   = tig << 3;
    const int wm   = wid * 16;

    const int b  = blockIdx.z;
    const int h  = blockIdx.y;
    const int t0 = blockIdx.x * 128;

#pragma unroll
    for (int w = 0; w < 16; w++) {
        int idx = tid + 256 * w;
        int r = idx >> 5, dw = idx & 31;
        sQ[dw * AQ2 + (r ^ ((dw & 3) << 3))] =
            qs[(size_t)(b * T_DIM + t0 + r) * 512 + h * 32 + dw];
    }

    float yacc[8][4];
#pragma unroll
    for (int dt = 0; dt < 8; dt++)
#pragma unroll
        for (int r = 0; r < 4; r++) yacc[dt][r] = 0.f;
    float m0r = -1e30f, m1r = -1e30f;
    float l0r = 0.f, l1r = 0.f;

    __syncthreads();

    for (int c = 0; c < 9; c++) {
        const int i0 = c * 64;
        // load K chunk (hi words only)
#pragma unroll
        for (int w = 0; w < 8; w++) {
            int idx = tid + 256 * w;
            int r = idx >> 5, dw = idx & 31;
            uint2 v = kvs[(size_t)(b * I_DIM + i0 + r) * 1024 + h * 32 + dw];
            sK[dw * AK2 + (r ^ ((dw & 3) << 3))] = v.x;
        }
        __syncthreads();

        float sacc[8][4];
#pragma unroll
        for (int nt = 0; nt < 8; nt++)
#pragma unroll
            for (int r = 0; r < 4; r++) sacc[nt][r] = 0.f;

#pragma unroll
        for (int ks = 0; ks < 4; ks++) {
            const int kwa = 8 * ks + tig;
            uint2 af[4];
            af[0] = sQ[kwa * AQ2 + ((wm + g) ^ t8)];
            af[1] = sQ[kwa * AQ2 + ((wm + g + 8) ^ t8)];
            af[2] = sQ[(kwa + 4) * AQ2 + ((wm + g) ^ t8)];
            af[3] = sQ[(kwa + 4) * AQ2 + ((wm + g + 8) ^ t8)];
#pragma unroll
            for (int nt = 0; nt < 8; nt++) {
                const int cc = 8 * nt + g;
                mma_split2(sacc[nt], af,
                           sK[kwa * AK2 + (cc ^ t8)],
                           sK[(kwa + 4) * AK2 + (cc ^ t8)]);
            }
        }

        // online softmax (log2 domain)
        float cm0 = -1e30f, cm1 = -1e30f;
#pragma unroll
        for (int nt = 0; nt < 8; nt++) {
            sacc[nt][0] *= SCALE_L2E; sacc[nt][1] *= SCALE_L2E;
            sacc[nt][2] *= SCALE_L2E; sacc[nt][3] *= SCALE_L2E;
            cm0 = fmaxf(cm0, fmaxf(sacc[nt][0], sacc[nt][1]));
            cm1 = fmaxf(cm1, fmaxf(sacc[nt][2], sacc[nt][3]));
        }
        cm0 = fmaxf(cm0, __shfl_xor_sync(0xffffffffu, cm0, 1));
        cm0 = fmaxf(cm0, __shfl_xor_sync(0xffffffffu, cm0, 2));
        cm1 = fmaxf(cm1, __shfl_xor_sync(0xffffffffu, cm1, 1));
        cm1 = fmaxf(cm1, __shfl_xor_sync(0xffffffffu, cm1, 2));

        const float mn0 = fmaxf(m0r, cm0);
        const float mn1 = fmaxf(m1r, cm1);
        const float f0 = exp2f(m0r - mn0);
        const float f1 = exp2f(m1r - mn1);

        float cs0 = 0.f, cs1 = 0.f;
#pragma unroll
        for (int nt = 0; nt < 8; nt++) {
            sacc[nt][0] = exp2f(sacc[nt][0] - mn0);
            sacc[nt][1] = exp2f(sacc[nt][1] - mn0);
            sacc[nt][2] = exp2f(sacc[nt][2] - mn1);
            sacc[nt][3] = exp2f(sacc[nt][3] - mn1);
            cs0 += sacc[nt][0] + sacc[nt][1];
            cs1 += sacc[nt][2] + sacc[nt][3];
        }
        cs0 += __shfl_xor_sync(0xffffffffu, cs0, 1);
        cs0 += __shfl_xor_sync(0xffffffffu, cs0, 2);
        cs1 += __shfl_xor_sync(0xffffffffu, cs1, 1);
        cs1 += __shfl_xor_sync(0xffffffffu, cs1, 2);

        l0r = l0r * f0 + cs0;  m0r = mn0;
        l1r = l1r * f1 + cs1;  m1r = mn1;
#pragma unroll
        for (int dt = 0; dt < 8; dt++) {
            yacc[dt][0] *= f0; yacc[dt][1] *= f0;
            yacc[dt][2] *= f1; yacc[dt][3] *= f1;
        }

        // load + repack V chunk (hi words): word (iw,d) = (V[2iw][d], V[2iw+1][d])
#pragma unroll
        for (int p = 0; p < 4; p++) {
            int P = tid + 256 * p;
            int iw = P >> 5, dv = P & 31;
            uint2 r0 = kvs[(size_t)(b * I_DIM + i0 + 2 * iw) * 1024 + 512 + h * 32 + dv];
            uint2 r1 = kvs[(size_t)(b * I_DIM + i0 + 2 * iw + 1) * 1024 + 512 + h * 32 + dv];
            sV[iw * AK2 + ((2 * dv) ^ ((iw & 3) << 3))]     = prmt(r0.x, r1.x, 0x5410);
            sV[iw * AK2 + ((2 * dv + 1) ^ ((iw & 3) << 3))] = prmt(r0.x, r1.x, 0x7632);
        }
        __syncthreads();

        // Y += P V  (P split -> A fragments)
#pragma unroll
        for (int ks = 0; ks < 4; ks++) {
            uint2 a[4];
            a[0] = splitw(sacc[2 * ks][0],     sacc[2 * ks][1]);
            a[1] = splitw(sacc[2 * ks][2],     sacc[2 * ks][3]);
            a[2] = splitw(sacc[2 * ks + 1][0], sacc[2 * ks + 1][1]);
            a[3] = splitw(sacc[2 * ks + 1][2], sacc[2 * ks + 1][3]);
            const int kwa = 8 * ks + tig;
#pragma unroll
            for (int dt = 0; dt < 8; dt++) {
                const int cc = 8 * dt + g;
                mma_split2(yacc[dt], a,
                           sV[kwa * AK2 + (cc ^ t8)],
                           sV[(kwa + 4) * AK2 + (cc ^ t8)]);
            }
        }
        __syncthreads();
    }

    const float inv0 = 1.0f / l0r;
    const float inv1 = 1.0f / l1r;
    const size_t r0 = (size_t)(b * T_DIM + t0 + wm + g);
#pragma unroll
    for (int dt = 0; dt < 8; dt++) {
        const int col = 8 * dt + 2 * tig;
        const int cw  = h * 32 + (col >> 1);
        ys[r0 * 512 + cw]       = splitw(yacc[dt][0] * inv0, yacc[dt][1] * inv0);
        ys[(r0 + 8) * 512 + cw] = splitw(yacc[dt][2] * inv1, yacc[dt][3] * inv1);
    }
}

// ---------------------------------------------------------------------------
// Launch
// ---------------------------------------------------------------------------
extern "C" void kernel_launch(void* const* d_in, const int* in_sizes, int n_in,
                              void* d_out, int out_size)
{
    const float* x   = (const float*)d_in[0];
    const float* enc = (const float*)d_in[1];
    const float* Wq  = (const float*)d_in[2];
    const float* bq  = (const float*)d_in[3];
    const float* Wkv = (const float*)d_in[4];
    const float* bkv = (const float*)d_in[5];
    const float* Wo  = (const float*)d_in[6];
    const float* bo  = (const float*)d_in[7];
    float* out = (float*)d_out;

    uint2 *xs, *es, *wqs, *wkvs, *wos, *qsp, *kvsp, *ysp;
    cudaGetSymbolAddress((void**)&xs,   g_xs);
    cudaGetSymbolAddress((void**)&es,   g_es);
    cudaGetSymbolAddress((void**)&wqs,  g_wqs);
    cudaGetSymbolAddress((void**)&wkvs, g_wkvs);
    cudaGetSymbolAddress((void**)&wos,  g_wos);
    cudaGetSymbolAddress((void**)&qsp,  g_qs);
    cudaGetSymbolAddress((void**)&kvsp, g_kvs);
    cudaGetSymbolAddress((void**)&ysp,  g_ys);

    cudaFuncSetAttribute(attn_flash,
                         cudaFuncAttributeMaxDynamicSharedMemorySize, ATTN_BYTES);

    // conversions (fp32 -> split planes)
    {
        int n;
        n = BATCH * T_DIM * C_DIM / 2;
        convert_split<<<(n + 255) / 256, 256>>>((const float2*)x, xs, n);
        n = BATCH * I_DIM * C_DIM / 2;
        convert_split<<<(n + 255) / 256, 256>>>((const float2*)enc, es, n);
        n = C_DIM * C_DIM / 2;
        convert_split<<<(n + 255) / 256, 256>>>((const float2*)Wq, wqs, n);
        n = 2 * C_DIM * C_DIM / 2;
        convert_split<<<(n + 255) / 256, 256>>>((const float2*)Wkv, wkvs, n);
        n = C_DIM * C_DIM / 2;
        convert_split<<<(n + 255) / 256, 256>>>((const float2*)Wo, wos, n);
    }

    // Q = x Wq^T + bq  -> split q
    gemm_split<true><<<dim3(C_DIM / 128, BATCH * T_DIM / 128), 256>>>(
        xs, wqs, bq, nullptr, qsp, BATCH * T_DIM, C_DIM, C_DIM / 2);

    // KV = enc Wkv^T + bkv -> split kv
    gemm_split<true><<<dim3(2 * C_DIM / 128, BATCH * I_DIM / 128), 256>>>(
        es, wkvs, bkv, nullptr, kvsp, BATCH * I_DIM, 2 * C_DIM, C_DIM / 2);

    // flash attention -> split y
    attn_flash<<<dim3(T_DIM / 128, N_HEAD, BATCH), 256, ATTN_BYTES>>>(
        qsp, kvsp, ysp);

    // out = y Wo^T + bo  (fp32)
    gemm_split<false><<<dim3(C_DIM / 128, BATCH * T_DIM / 128), 256>>>(
        ysp, wos, bo, out, nullptr, BATCH * T_DIM, C_DIM, C_DIM / 2);
}

// round 15
// speedup vs baseline: 1.2089x; 1.0052x over previous
#include <cuda_runtime.h>
#include <cuda_bf16.h>
#include <cuda_fp16.h>
#include <math.h>

// Problem constants
#define BATCH  8
#define T_DIM  1024
#define I_DIM  576
#define C_DIM  1024
#define N_HEAD 16
#define HD     64

// ---------------------------------------------------------------------------
// Scratch: split-fp16 planes. uint2 = (f16x2 hi, f16x2 lo), pairs along last
// dim: word w of a row covers elements (2w, 2w+1).
// ---------------------------------------------------------------------------
__device__ uint2 g_xs  [BATCH * T_DIM * C_DIM / 2];
__device__ uint2 g_es  [BATCH * I_DIM * C_DIM / 2];
__device__ uint2 g_wqs [C_DIM * C_DIM / 2];
__device__ uint2 g_wkvs[2 * C_DIM * C_DIM / 2];
__device__ uint2 g_wos [C_DIM * C_DIM / 2];
__device__ uint2 g_qs  [BATCH * T_DIM * C_DIM / 2];
__device__ uint2 g_kvs [BATCH * I_DIM * 2 * C_DIM / 2];
__device__ uint2 g_ys  [BATCH * T_DIM * C_DIM / 2];

// ---------------------------------------------------------------------------
// helpers (fp16 2-term split)
// ---------------------------------------------------------------------------
__device__ __forceinline__ unsigned pack_h2(float x, float y) {
    __half2 t = __floats2half2_rn(x, y);
    return *reinterpret_cast<unsigned*>(&t);
}
__device__ __forceinline__ uint2 splitw(float x, float y) {
    float hx = __half2float(__float2half(x));
    float hy = __half2float(__float2half(y));
    return make_uint2(pack_h2(hx, hy), pack_h2(x - hx, y - hy));
}
__device__ __forceinline__ unsigned prmt(unsigned a, unsigned b, unsigned s) {
    unsigned d;
    asm("prmt.b32 %0,%1,%2,%3;" : "=r"(d) : "r"(a), "r"(b), "r"(s));
    return d;
}
__device__ __forceinline__ void mma_f16(float* c,
    unsigned a0, unsigned a1, unsigned a2, unsigned a3,
    unsigned b0, unsigned b1)
{
    asm volatile(
        "mma.sync.aligned.m16n8k16.row.col.f32.f16.f16.f32 "
        "{%0,%1,%2,%3},{%4,%5,%6,%7},{%8,%9},{%0,%1,%2,%3};\n"
        : "+f"(c[0]), "+f"(c[1]), "+f"(c[2]), "+f"(c[3])
        : "r"(a0), "r"(a1), "r"(a2), "r"(a3), "r"(b0), "r"(b1));
}
// 2-term split product: (ah + al) * bh
__device__ __forceinline__ void mma_split2(float* c, const uint2 a[4],
                                           unsigned b0, unsigned b1) {
    mma_f16(c, a[0].x, a[1].x, a[2].x, a[3].x, b0, b1);
    mma_f16(c, a[0].y, a[1].y, a[2].y, a[3].y, b0, b1);
}

// ---------------------------------------------------------------------------
// conversion: fp32 tensor -> split planes
// ---------------------------------------------------------------------------
__global__ __launch_bounds__(256) void convert_split(
    const float2* __restrict__ src, uint2* __restrict__ dst, int n)
{
    int i = blockIdx.x * 256 + threadIdx.x;
    if (i < n) { float2 v = src[i]; dst[i] = splitw(v.x, v.y); }
}

// ---------------------------------------------------------------------------
// GEMM NT on split planes: C[M,N] = A[M,K] B[N,K]^T + bias
// Block 128x128, stage = k16 (8 words), double-buffered. 8 warps (4m x 2n),
// warp tile 32x64. A smem keeps (hi,lo); B smem stores hi only.
// ---------------------------------------------------------------------------
#define MS2 132
__device__ __forceinline__ int sidx(int kw, int m) {
    return kw * MS2 + (m ^ ((kw & 3) << 3));
}
#define STG (8 * MS2)

template<bool SPLIT_OUT>
__global__ __launch_bounds__(256) void gemm_split(
    const uint2* __restrict__ AS, const uint2* __restrict__ BS,
    const float* __restrict__ bias, float* __restrict__ Cf,
    uint2* __restrict__ Cs, int M, int N, int KW)
{
    __shared__ uint2    sA[2 * STG];
    __shared__ unsigned sB[2 * STG];

    const int tid  = threadIdx.x;
    const int m0   = blockIdx.y * 128;
    const int n0   = blockIdx.x * 128;
    const int wid  = tid >> 5;
    const int lane = tid & 31;
    const int g    = lane >> 2;
    const int tig  = lane & 3;
    const int t8   = tig << 3;
    const int wm   = (wid >> 1) * 32;   // 4 m-groups
    const int wn   = (wid & 1) * 64;    // 2 n-groups

    const int lr = tid >> 1;          // 0..127
    const int jb = (tid & 1) * 4;     // word offset 0 or 4

    const uint4* Ag = (const uint4*)(AS + (size_t)(m0 + lr) * KW + jb);
    const uint4* Bg = (const uint4*)(BS + (size_t)(n0 + lr) * KW + jb);

    float acc[2][8][4];
#pragma unroll
    for (int i = 0; i < 2; i++)
#pragma unroll
        for (int j = 0; j < 8; j++)
#pragma unroll
            for (int r = 0; r < 4; r++) acc[i][j][r] = 0.f;

    const int NS = KW >> 3;
    uint4 a0, a1, b0, b1;

    // prologue: stage 0
    a0 = Ag[0]; a1 = Ag[1]; b0 = Bg[0]; b1 = Bg[1];
    {
        sA[sidx(jb + 0, lr)] = make_uint2(a0.x, a0.y);
        sA[sidx(jb + 1, lr)] = make_uint2(a0.z, a0.w);
        sA[sidx(jb + 2, lr)] = make_uint2(a1.x, a1.y);
        sA[sidx(jb + 3, lr)] = make_uint2(a1.z, a1.w);
        sB[sidx(jb + 0, lr)] = b0.x;
        sB[sidx(jb + 1, lr)] = b0.z;
        sB[sidx(jb + 2, lr)] = b1.x;
        sB[sidx(jb + 3, lr)] = b1.z;
    }
    __syncthreads();

    for (int s = 0; s < NS; s++) {
        const int cur = s & 1;
        if (s + 1 < NS) {
            const uint4* ap = Ag + (size_t)(s + 1) * 4;
            const uint4* bp = Bg + (size_t)(s + 1) * 4;
            a0 = ap[0]; a1 = ap[1]; b0 = bp[0]; b1 = bp[1];
        }

        const uint2*    sa = sA + cur * STG;
        const unsigned* sb = sB + cur * STG;

        uint2 af[2][4];
#pragma unroll
        for (int mt = 0; mt < 2; mt++) {
            const int r = wm + 16 * mt + g;
            af[mt][0] = sa[tig * MS2 + (r ^ t8)];
            af[mt][1] = sa[tig * MS2 + ((r + 8) ^ t8)];
            af[mt][2] = sa[(tig + 4) * MS2 + (r ^ t8)];
            af[mt][3] = sa[(tig + 4) * MS2 + ((r + 8) ^ t8)];
        }
        unsigned bf[8][2];
#pragma unroll
        for (int nt = 0; nt < 8; nt++) {
            const int c = wn + 8 * nt + g;
            bf[nt][0] = sb[tig * MS2 + (c ^ t8)];
            bf[nt][1] = sb[(tig + 4) * MS2 + (c ^ t8)];
        }
#pragma unroll
        for (int mt = 0; mt < 2; mt++)
#pragma unroll
            for (int nt = 0; nt < 8; nt++)
                mma_split2(acc[mt][nt], af[mt], bf[nt][0], bf[nt][1]);

        if (s + 1 < NS) {
            uint2*    dA = sA + ((s + 1) & 1) * STG;
            unsigned* dB = sB + ((s + 1) & 1) * STG;
            dA[sidx(jb + 0, lr)] = make_uint2(a0.x, a0.y);
            dA[sidx(jb + 1, lr)] = make_uint2(a0.z, a0.w);
            dA[sidx(jb + 2, lr)] = make_uint2(a1.x, a1.y);
            dA[sidx(jb + 3, lr)] = make_uint2(a1.z, a1.w);
            dB[sidx(jb + 0, lr)] = b0.x;
            dB[sidx(jb + 1, lr)] = b0.z;
            dB[sidx(jb + 2, lr)] = b1.x;
            dB[sidx(jb + 3, lr)] = b1.z;
        }
        __syncthreads();
    }

    // epilogue
#pragma unroll
    for (int mt = 0; mt < 2; mt++) {
        const int r0 = m0 + wm + 16 * mt + g;
#pragma unroll
        for (int nt = 0; nt < 8; nt++) {
            const int cb = n0 + wn + 8 * nt + 2 * tig;
            const float v0 = bias[cb], v1 = bias[cb + 1];
            if (SPLIT_OUT) {
                Cs[(size_t)r0 * (N >> 1) + (cb >> 1)] =
                    splitw(acc[mt][nt][0] + v0, acc[mt][nt][1] + v1);
                Cs[(size_t)(r0 + 8) * (N >> 1) + (cb >> 1)] =
                    splitw(acc[mt][nt][2] + v0, acc[mt][nt][3] + v1);
            } else {
                *(float2*)(Cf + (size_t)r0 * N + cb) =
                    make_float2(acc[mt][nt][0] + v0, acc[mt][nt][1] + v1);
                *(float2*)(Cf + (size_t)(r0 + 8) * N + cb) =
                    make_float2(acc[mt][nt][2] + v0, acc[mt][nt][3] + v1);
            }
        }
    }
}

// ---------------------------------------------------------------------------
// Flash attention via 2-term split-mma. Q split (A operand); K/V hi-only (B).
// Block = 128 t-rows x (b,h). 8 warps, warp w owns rows [16w, 16w+16).
// __launch_bounds__(256, 2): co-resident CTA overlaps softmax/repack phases.
// ---------------------------------------------------------------------------
#define AQ2 136   // sQ stride (uint2)
#define AK2 68    // sK/sV stride (unsigned)
#define ATTN_BYTES (32 * AQ2 * 8 + 2 * 32 * AK2 * 4)   // ~52 KB
#define SCALE_L2E 0.1803368801111204f   // 0.125 * log2(e)

__global__ __launch_bounds__(256, 2) void attn_flash(
    const uint2* __restrict__ qs, const uint2* __restrict__ kvs,
    uint2* __restrict__ ys)
{
    extern __shared__ char smraw[];
    uint2*    sQ = (uint2*)smraw;                          // [32 kw][128 r]
    unsigned* sK = (unsigned*)(smraw + 32 * AQ2 * 8);      // [32 kw][64 r]
    unsigned* sV = sK + 32 * AK2;                          // [32 iw][64 d]

    const int tid  = threadIdx.x;
    const int wid  = tid >> 5;
    const int lane = tid & 31;
    const int g    = lane >> 2;
    const int tig  = lane & 3;
    const int t8   = tig << 3;
    const int wm   = wid * 16;

    const int b  = blockIdx.z;
    const int h  = blockIdx.y;
    const int t0 = blockIdx.x * 128;

#pragma unroll
    for (int w = 0; w < 16; w++) {
        int idx = tid + 256 * w;
        int r = idx >> 5, dw = idx & 31;
        sQ[dw * AQ2 + (r ^ ((dw & 3) << 3))] =
            qs[(size_t)(b * T_DIM + t0 + r) * 512 + h * 32 + dw];
    }

    float yacc[8][4];
#pragma unroll
    for (int dt = 0; dt < 8; dt++)
#pragma unroll
        for (int r = 0; r < 4; r++) yacc[dt][r] = 0.f;
    float m0r = -1e30f, m1r = -1e30f;
    float l0r = 0.f, l1r = 0.f;

    __syncthreads();

    for (int c = 0; c < 9; c++) {
        const int i0 = c * 64;
        // load K chunk (hi words only)
#pragma unroll
        for (int w = 0; w < 8; w++) {
            int idx = tid + 256 * w;
            int r = idx >> 5, dw = idx & 31;
            uint2 v = kvs[(size_t)(b * I_DIM + i0 + r) * 1024 + h * 32 + dw];
            sK[dw * AK2 + (r ^ ((dw & 3) << 3))] = v.x;
        }
        __syncthreads();

        float sacc[8][4];
#pragma unroll
        for (int nt = 0; nt < 8; nt++)
#pragma unroll
            for (int r = 0; r < 4; r++) sacc[nt][r] = 0.f;

#pragma unroll
        for (int ks = 0; ks < 4; ks++) {
            const int kwa = 8 * ks + tig;
            uint2 af[4];
            af[0] = sQ[kwa * AQ2 + ((wm + g) ^ t8)];
            af[1] = sQ[kwa * AQ2 + ((wm + g + 8) ^ t8)];
            af[2] = sQ[(kwa + 4) * AQ2 + ((wm + g) ^ t8)];
            af[3] = sQ[(kwa + 4) * AQ2 + ((wm + g + 8) ^ t8)];
#pragma unroll
            for (int nt = 0; nt < 8; nt++) {
                const int cc = 8 * nt + g;
                mma_split2(sacc[nt], af,
                           sK[kwa * AK2 + (cc ^ t8)],
                           sK[(kwa + 4) * AK2 + (cc ^ t8)]);
            }
        }

        // online softmax (log2 domain)
        float cm0 = -1e30f, cm1 = -1e30f;
#pragma unroll
        for (int nt = 0; nt < 8; nt++) {
            sacc[nt][0] *= SCALE_L2E; sacc[nt][1] *= SCALE_L2E;
            sacc[nt][2] *= SCALE_L2E; sacc[nt][3] *= SCALE_L2E;
            cm0 = fmaxf(cm0, fmaxf(sacc[nt][0], sacc[nt][1]));
            cm1 = fmaxf(cm1, fmaxf(sacc[nt][2], sacc[nt][3]));
        }
        cm0 = fmaxf(cm0, __shfl_xor_sync(0xffffffffu, cm0, 1));
        cm0 = fmaxf(cm0, __shfl_xor_sync(0xffffffffu, cm0, 2));
        cm1 = fmaxf(cm1, __shfl_xor_sync(0xffffffffu, cm1, 1));
        cm1 = fmaxf(cm1, __shfl_xor_sync(0xffffffffu, cm1, 2));

        const float mn0 = fmaxf(m0r, cm0);
        const float mn1 = fmaxf(m1r, cm1);
        const float f0 = exp2f(m0r - mn0);
        const float f1 = exp2f(m1r - mn1);

        float cs0 = 0.f, cs1 = 0.f;
#pragma unroll
        for (int nt = 0; nt < 8; nt++) {
            sacc[nt][0] = exp2f(sacc[nt][0] - mn0);
            sacc[nt][1] = exp2f(sacc[nt][1] - mn0);
            sacc[nt][2] = exp2f(sacc[nt][2] - mn1);
            sacc[nt][3] = exp2f(sacc[nt][3] - mn1);
            cs0 += sacc[nt][0] + sacc[nt][1];
            cs1 += sacc[nt][2] + sacc[nt][3];
        }
        cs0 += __shfl_xor_sync(0xffffffffu, cs0, 1);
        cs0 += __shfl_xor_sync(0xffffffffu, cs0, 2);
        cs1 += __shfl_xor_sync(0xffffffffu, cs1, 1);
        cs1 += __shfl_xor_sync(0xffffffffu, cs1, 2);

        l0r = l0r * f0 + cs0;  m0r = mn0;
        l1r = l1r * f1 + cs1;  m1r = mn1;
#pragma unroll
        for (int dt = 0; dt < 8; dt++) {
            yacc[dt][0] *= f0; yacc[dt][1] *= f0;
            yacc[dt][2] *= f1; yacc[dt][3] *= f1;
        }

        // load + repack V chunk (hi words): word (iw,d) = (V[2iw][d], V[2iw+1][d])
#pragma unroll
        for (int p = 0; p < 4; p++) {
            int P = tid + 256 * p;
            int iw = P >> 5, dv = P & 31;
            uint2 r0 = kvs[(size_t)(b * I_DIM + i0 + 2 * iw) * 1024 + 512 + h * 32 + dv];
            uint2 r1 = kvs[(size_t)(b * I_DIM + i0 + 2 * iw + 1) * 1024 + 512 + h * 32 + dv];
            sV[iw * AK2 + ((2 * dv) ^ ((iw & 3) << 3))]     = prmt(r0.x, r1.x, 0x5410);
            sV[iw * AK2 + ((2 * dv + 1) ^ ((iw & 3) << 3))] = prmt(r0.x, r1.x, 0x7632);
        }
        __syncthreads();

        // Y += P V  (P split -> A fragments)
#pragma unroll
        for (int ks = 0; ks < 4; ks++) {
            uint2 a[4];
            a[0] = splitw(sacc[2 * ks][0],     sacc[2 * ks][1]);
            a[1] = splitw(sacc[2 * ks][2],     sacc[2 * ks][3]);
            a[2] = splitw(sacc[2 * ks + 1][0], sacc[2 * ks + 1][1]);
            a[3] = splitw(sacc[2 * ks + 1][2], sacc[2 * ks + 1][3]);
            const int kwa = 8 * ks + tig;
#pragma unroll
            for (int dt = 0; dt < 8; dt++) {
                const int cc = 8 * dt + g;
                mma_split2(yacc[dt], a,
                           sV[kwa * AK2 + (cc ^ t8)],
                           sV[(kwa + 4) * AK2 + (cc ^ t8)]);
            }
        }
        __syncthreads();
    }

    const float inv0 = 1.0f / l0r;
    const float inv1 = 1.0f / l1r;
    const size_t r0 = (size_t)(b * T_DIM + t0 + wm + g);
#pragma unroll
    for (int dt = 0; dt < 8; dt++) {
        const int col = 8 * dt + 2 * tig;
        const int cw  = h * 32 + (col >> 1);
        ys[r0 * 512 + cw]       = splitw(yacc[dt][0] * inv0, yacc[dt][1] * inv0);
        ys[(r0 + 8) * 512 + cw] = splitw(yacc[dt][2] * inv1, yacc[dt][3] * inv1);
    }
}

// ---------------------------------------------------------------------------
// Launch
// ---------------------------------------------------------------------------
extern "C" void kernel_launch(void* const* d_in, const int* in_sizes, int n_in,
                              void* d_out, int out_size)
{
    const float* x   = (const float*)d_in[0];
    const float* enc = (const float*)d_in[1];
    const float* Wq  = (const float*)d_in[2];
    const float* bq  = (const float*)d_in[3];
    const float* Wkv = (const float*)d_in[4];
    const float* bkv = (const float*)d_in[5];
    const float* Wo  = (const float*)d_in[6];
    const float* bo  = (const float*)d_in[7];
    float* out = (float*)d_out;

    uint2 *xs, *es, *wqs, *wkvs, *wos, *qsp, *kvsp, *ysp;
    cudaGetSymbolAddress((void**)&xs,   g_xs);
    cudaGetSymbolAddress((void**)&es,   g_es);
    cudaGetSymbolAddress((void**)&wqs,  g_wqs);
    cudaGetSymbolAddress((void**)&wkvs, g_wkvs);
    cudaGetSymbolAddress((void**)&wos,  g_wos);
    cudaGetSymbolAddress((void**)&qsp,  g_qs);
    cudaGetSymbolAddress((void**)&kvsp, g_kvs);
    cudaGetSymbolAddress((void**)&ysp,  g_ys);

    cudaFuncSetAttribute(attn_flash,
                         cudaFuncAttributeMaxDynamicSharedMemorySize, ATTN_BYTES);

    // conversions (fp32 -> split planes)
    {
        int n;
        n = BATCH * T_DIM * C_DIM / 2;
        convert_split<<<(n + 255) / 256, 256>>>((const float2*)x, xs, n);
        n = BATCH * I_DIM * C_DIM / 2;
        convert_split<<<(n + 255) / 256, 256>>>((const float2*)enc, es, n);
        n = C_DIM * C_DIM / 2;
        convert_split<<<(n + 255) / 256, 256>>>((const float2*)Wq, wqs, n);
        n = 2 * C_DIM * C_DIM / 2;
        convert_split<<<(n + 255) / 256, 256>>>((const float2*)Wkv, wkvs, n);
        n = C_DIM * C_DIM / 2;
        convert_split<<<(n + 255) / 256, 256>>>((const float2*)Wo, wos, n);
    }

    // Q = x Wq^T + bq  -> split q
    gemm_split<true><<<dim3(C_DIM / 128, BATCH * T_DIM / 128), 256>>>(
        xs, wqs, bq, nullptr, qsp, BATCH * T_DIM, C_DIM, C_DIM / 2);

    // KV = enc Wkv^T + bkv -> split kv
    gemm_split<true><<<dim3(2 * C_DIM / 128, BATCH * I_DIM / 128), 256>>>(
        es, wkvs, bkv, nullptr, kvsp, BATCH * I_DIM, 2 * C_DIM, C_DIM / 2);

    // flash attention -> split y
    attn_flash<<<dim3(T_DIM / 128, N_HEAD, BATCH), 256, ATTN_BYTES>>>(
        qsp, kvsp, ysp);

    // out = y Wo^T + bo  (fp32)
    gemm_split<false><<<dim3(C_DIM / 128, BATCH * T_DIM / 128), 256>>>(
        ysp, wos, bo, out, nullptr, BATCH * T_DIM, C_DIM, C_DIM / 2);
}

// round 16
// speedup vs baseline: 1.5366x; 1.2710x over previous
#include <cuda_runtime.h>
#include <cuda_bf16.h>
#include <cuda_fp16.h>
#include <math.h>

// Problem constants
#define BATCH  8
#define T_DIM  1024
#define I_DIM  576
#define C_DIM  1024
#define N_HEAD 16
#define HD     64

// ---------------------------------------------------------------------------
// Scratch planes.
// Split plane (A operands): uint2 = (f16x2 hi, f16x2 lo), pairs along last dim.
// Hi plane (B operands):    unsigned = f16x2 hi, pairs along last dim.
// ---------------------------------------------------------------------------
__device__ uint2    g_xs  [BATCH * T_DIM * C_DIM / 2];
__device__ uint2    g_es  [BATCH * I_DIM * C_DIM / 2];
__device__ unsigned g_wqh [C_DIM * C_DIM / 2];
__device__ unsigned g_wkvh[2 * C_DIM * C_DIM / 2];
__device__ unsigned g_woh [C_DIM * C_DIM / 2];
__device__ uint2    g_qs  [BATCH * T_DIM * C_DIM / 2];
__device__ unsigned g_kvh [BATCH * I_DIM * 2 * C_DIM / 2];
__device__ uint2    g_ys  [BATCH * T_DIM * C_DIM / 2];

// ---------------------------------------------------------------------------
// helpers (fp16 2-term split)
// ---------------------------------------------------------------------------
__device__ __forceinline__ unsigned pack_h2(float x, float y) {
    __half2 t = __floats2half2_rn(x, y);
    return *reinterpret_cast<unsigned*>(&t);
}
__device__ __forceinline__ uint2 splitw(float x, float y) {
    float hx = __half2float(__float2half(x));
    float hy = __half2float(__float2half(y));
    return make_uint2(pack_h2(hx, hy), pack_h2(x - hx, y - hy));
}
__device__ __forceinline__ unsigned prmt(unsigned a, unsigned b, unsigned s) {
    unsigned d;
    asm("prmt.b32 %0,%1,%2,%3;" : "=r"(d) : "r"(a), "r"(b), "r"(s));
    return d;
}
__device__ __forceinline__ void mma_f16(float* c,
    unsigned a0, unsigned a1, unsigned a2, unsigned a3,
    unsigned b0, unsigned b1)
{
    asm volatile(
        "mma.sync.aligned.m16n8k16.row.col.f32.f16.f16.f32 "
        "{%0,%1,%2,%3},{%4,%5,%6,%7},{%8,%9},{%0,%1,%2,%3};\n"
        : "+f"(c[0]), "+f"(c[1]), "+f"(c[2]), "+f"(c[3])
        : "r"(a0), "r"(a1), "r"(a2), "r"(a3), "r"(b0), "r"(b1));
}
// 2-term split product: (ah + al) * bh
__device__ __forceinline__ void mma_split2(float* c, const uint2 a[4],
                                           unsigned b0, unsigned b1) {
    mma_f16(c, a[0].x, a[1].x, a[2].x, a[3].x, b0, b1);
    mma_f16(c, a[0].y, a[1].y, a[2].y, a[3].y, b0, b1);
}

// ---------------------------------------------------------------------------
// conversions: fp32 -> split plane / hi plane
// ---------------------------------------------------------------------------
__global__ __launch_bounds__(256) void convert_split(
    const float2* __restrict__ src, uint2* __restrict__ dst, int n)
{
    int i = blockIdx.x * 256 + threadIdx.x;
    if (i < n) { float2 v = src[i]; dst[i] = splitw(v.x, v.y); }
}
__global__ __launch_bounds__(256) void convert_hi(
    const float2* __restrict__ src, unsigned* __restrict__ dst, int n)
{
    int i = blockIdx.x * 256 + threadIdx.x;
    if (i < n) { float2 v = src[i]; dst[i] = pack_h2(v.x, v.y); }
}

// ---------------------------------------------------------------------------
// GEMM NT: C[M,N] = A[M,K] B[N,K]^T + bias.  A = split plane, B = hi plane.
// Block 128x128, stage = k16 (8 words), double-buffered. 8 warps (4m x 2n),
// warp tile 32x64. OUT: 0 = fp32, 1 = split uint2, 2 = hi unsigned.
// ---------------------------------------------------------------------------
#define MS2 132
__device__ __forceinline__ int sidx(int kw, int m) {
    return kw * MS2 + (m ^ ((kw & 3) << 3));
}
#define STG (8 * MS2)

template<int OUT>
__global__ __launch_bounds__(256) void gemm_split(
    const uint2* __restrict__ AS, const unsigned* __restrict__ BH,
    const float* __restrict__ bias, float* __restrict__ Cf,
    uint2* __restrict__ Cs, unsigned* __restrict__ Ch, int M, int N, int KW)
{
    __shared__ uint2    sA[2 * STG];
    __shared__ unsigned sB[2 * STG];

    const int tid  = threadIdx.x;
    const int m0   = blockIdx.y * 128;
    const int n0   = blockIdx.x * 128;
    const int wid  = tid >> 5;
    const int lane = tid & 31;
    const int g    = lane >> 2;
    const int tig  = lane & 3;
    const int t8   = tig << 3;
    const int wm   = (wid >> 1) * 32;   // 4 m-groups
    const int wn   = (wid & 1) * 64;    // 2 n-groups

    const int lr = tid >> 1;          // 0..127
    const int jb = (tid & 1) * 4;     // word offset 0 or 4

    const uint4* Ag = (const uint4*)(AS + (size_t)(m0 + lr) * KW + jb);
    const uint4* Bg = (const uint4*)(BH + (size_t)(n0 + lr) * KW + jb);

    float acc[2][8][4];
#pragma unroll
    for (int i = 0; i < 2; i++)
#pragma unroll
        for (int j = 0; j < 8; j++)
#pragma unroll
            for (int r = 0; r < 4; r++) acc[i][j][r] = 0.f;

    const int NS = KW >> 3;
    uint4 a0, a1, b0;

    // prologue: stage 0  (A: 2 uint4 = 4 split words; B: 1 uint4 = 4 hi words)
    a0 = Ag[0]; a1 = Ag[1]; b0 = Bg[0];
    {
        sA[sidx(jb + 0, lr)] = make_uint2(a0.x, a0.y);
        sA[sidx(jb + 1, lr)] = make_uint2(a0.z, a0.w);
        sA[sidx(jb + 2, lr)] = make_uint2(a1.x, a1.y);
        sA[sidx(jb + 3, lr)] = make_uint2(a1.z, a1.w);
        sB[sidx(jb + 0, lr)] = b0.x;
        sB[sidx(jb + 1, lr)] = b0.y;
        sB[sidx(jb + 2, lr)] = b0.z;
        sB[sidx(jb + 3, lr)] = b0.w;
    }
    __syncthreads();

    for (int s = 0; s < NS; s++) {
        const int cur = s & 1;
        if (s + 1 < NS) {
            const uint4* ap = Ag + (size_t)(s + 1) * 4;
            a0 = ap[0]; a1 = ap[1];
            b0 = Bg[(size_t)(s + 1) * 2];
        }

        const uint2*    sa = sA + cur * STG;
        const unsigned* sb = sB + cur * STG;

        uint2 af[2][4];
#pragma unroll
        for (int mt = 0; mt < 2; mt++) {
            const int r = wm + 16 * mt + g;
            af[mt][0] = sa[tig * MS2 + (r ^ t8)];
            af[mt][1] = sa[tig * MS2 + ((r + 8) ^ t8)];
            af[mt][2] = sa[(tig + 4) * MS2 + (r ^ t8)];
            af[mt][3] = sa[(tig + 4) * MS2 + ((r + 8) ^ t8)];
        }
        unsigned bf[8][2];
#pragma unroll
        for (int nt = 0; nt < 8; nt++) {
            const int c = wn + 8 * nt + g;
            bf[nt][0] = sb[tig * MS2 + (c ^ t8)];
            bf[nt][1] = sb[(tig + 4) * MS2 + (c ^ t8)];
        }
#pragma unroll
        for (int mt = 0; mt < 2; mt++)
#pragma unroll
            for (int nt = 0; nt < 8; nt++)
                mma_split2(acc[mt][nt], af[mt], bf[nt][0], bf[nt][1]);

        if (s + 1 < NS) {
            uint2*    dA = sA + ((s + 1) & 1) * STG;
            unsigned* dB = sB + ((s + 1) & 1) * STG;
            dA[sidx(jb + 0, lr)] = make_uint2(a0.x, a0.y);
            dA[sidx(jb + 1, lr)] = make_uint2(a0.z, a0.w);
            dA[sidx(jb + 2, lr)] = make_uint2(a1.x, a1.y);
            dA[sidx(jb + 3, lr)] = make_uint2(a1.z, a1.w);
            dB[sidx(jb + 0, lr)] = b0.x;
            dB[sidx(jb + 1, lr)] = b0.y;
            dB[sidx(jb + 2, lr)] = b0.z;
            dB[sidx(jb + 3, lr)] = b0.w;
        }
        __syncthreads();
    }

    // epilogue
#pragma unroll
    for (int mt = 0; mt < 2; mt++) {
        const int r0 = m0 + wm + 16 * mt + g;
#pragma unroll
        for (int nt = 0; nt < 8; nt++) {
            const int cb = n0 + wn + 8 * nt + 2 * tig;
            const float v0 = bias[cb], v1 = bias[cb + 1];
            const float c0 = acc[mt][nt][0] + v0, c1 = acc[mt][nt][1] + v1;
            const float c2 = acc[mt][nt][2] + v0, c3 = acc[mt][nt][3] + v1;
            if (OUT == 1) {
                Cs[(size_t)r0 * (N >> 1) + (cb >> 1)]       = splitw(c0, c1);
                Cs[(size_t)(r0 + 8) * (N >> 1) + (cb >> 1)] = splitw(c2, c3);
            } else if (OUT == 2) {
                Ch[(size_t)r0 * (N >> 1) + (cb >> 1)]       = pack_h2(c0, c1);
                Ch[(size_t)(r0 + 8) * (N >> 1) + (cb >> 1)] = pack_h2(c2, c3);
            } else {
                *(float2*)(Cf + (size_t)r0 * N + cb)       = make_float2(c0, c1);
                *(float2*)(Cf + (size_t)(r0 + 8) * N + cb) = make_float2(c2, c3);
            }
        }
    }
}

// ---------------------------------------------------------------------------
// Flash attention. Q split (A); K/V from hi plane (B). P hi-only for PV.
// Block = 128 t-rows x (b,h). 8 warps, warp w owns rows [16w, 16w+16).
// Per chunk: load K + load/repack V, sync, QK mma, softmax (log2), PV mma, sync.
// ---------------------------------------------------------------------------
#define AQ2 136   // sQ stride (uint2)
#define AK2 68    // sK/sV stride (unsigned)
#define ATTN_BYTES (32 * AQ2 * 8 + 2 * 32 * AK2 * 4)   // ~52 KB
#define SCALE_L2E 0.1803368801111204f   // 0.125 * log2(e)

__global__ __launch_bounds__(256) void attn_flash(
    const uint2* __restrict__ qs, const unsigned* __restrict__ kvh,
    uint2* __restrict__ ys)
{
    extern __shared__ char smraw[];
    uint2*    sQ = (uint2*)smraw;                          // [32 kw][128 r]
    unsigned* sK = (unsigned*)(smraw + 32 * AQ2 * 8);      // [32 kw][64 r]
    unsigned* sV = sK + 32 * AK2;                          // [32 iw][64 d]

    const int tid  = threadIdx.x;
    const int wid  = tid >> 5;
    const int lane = tid & 31;
    const int g    = lane >> 2;
    const int tig  = lane & 3;
    const int t8   = tig << 3;
    const int wm   = wid * 16;

    const int b  = blockIdx.z;
    const int h  = blockIdx.y;
    const int t0 = blockIdx.x * 128;

#pragma unroll
    for (int w = 0; w < 16; w++) {
        int idx = tid + 256 * w;
        int r = idx >> 5, dw = idx & 31;
        sQ[dw * AQ2 + (r ^ ((dw & 3) << 3))] =
            qs[(size_t)(b * T_DIM + t0 + r) * 512 + h * 32 + dw];
    }

    float yacc[8][4];
#pragma unroll
    for (int dt = 0; dt < 8; dt++)
#pragma unroll
        for (int r = 0; r < 4; r++) yacc[dt][r] = 0.f;
    float m0r = -1e30f, m1r = -1e30f;
    float l0r = 0.f, l1r = 0.f;

    __syncthreads();

    for (int c = 0; c < 9; c++) {
        const int i0 = c * 64;
        // load K chunk (hi plane): word (dw, r)
#pragma unroll
        for (int w = 0; w < 8; w++) {
            int idx = tid + 256 * w;
            int r = idx >> 5, dw = idx & 31;
            sK[dw * AK2 + (r ^ ((dw & 3) << 3))] =
                kvh[(size_t)(b * I_DIM + i0 + r) * 1024 + h * 32 + dw];
        }
        // load + repack V chunk (hi plane): word (iw,d) = (V[2iw][d], V[2iw+1][d])
#pragma unroll
        for (int p = 0; p < 4; p++) {
            int P = tid + 256 * p;
            int iw = P >> 5, dv = P & 31;
            unsigned r0 = kvh[(size_t)(b * I_DIM + i0 + 2 * iw) * 1024 + 512 + h * 32 + dv];
            unsigned r1 = kvh[(size_t)(b * I_DIM + i0 + 2 * iw + 1) * 1024 + 512 + h * 32 + dv];
            sV[iw * AK2 + ((2 * dv) ^ ((iw & 3) << 3))]     = prmt(r0, r1, 0x5410);
            sV[iw * AK2 + ((2 * dv + 1) ^ ((iw & 3) << 3))] = prmt(r0, r1, 0x7632);
        }
        __syncthreads();

        // S = Q K^T
        float sacc[8][4];
#pragma unroll
        for (int nt = 0; nt < 8; nt++)
#pragma unroll
            for (int r = 0; r < 4; r++) sacc[nt][r] = 0.f;

#pragma unroll
        for (int ks = 0; ks < 4; ks++) {
            const int kwa = 8 * ks + tig;
            uint2 af[4];
            af[0] = sQ[kwa * AQ2 + ((wm + g) ^ t8)];
            af[1] = sQ[kwa * AQ2 + ((wm + g + 8) ^ t8)];
            af[2] = sQ[(kwa + 4) * AQ2 + ((wm + g) ^ t8)];
            af[3] = sQ[(kwa + 4) * AQ2 + ((wm + g + 8) ^ t8)];
#pragma unroll
            for (int nt = 0; nt < 8; nt++) {
                const int cc = 8 * nt + g;
                mma_split2(sacc[nt], af,
                           sK[kwa * AK2 + (cc ^ t8)],
                           sK[(kwa + 4) * AK2 + (cc ^ t8)]);
            }
        }

        // online softmax (log2 domain)
        float cm0 = -1e30f, cm1 = -1e30f;
#pragma unroll
        for (int nt = 0; nt < 8; nt++) {
            sacc[nt][0] *= SCALE_L2E; sacc[nt][1] *= SCALE_L2E;
            sacc[nt][2] *= SCALE_L2E; sacc[nt][3] *= SCALE_L2E;
            cm0 = fmaxf(cm0, fmaxf(sacc[nt][0], sacc[nt][1]));
            cm1 = fmaxf(cm1, fmaxf(sacc[nt][2], sacc[nt][3]));
        }
        cm0 = fmaxf(cm0, __shfl_xor_sync(0xffffffffu, cm0, 1));
        cm0 = fmaxf(cm0, __shfl_xor_sync(0xffffffffu, cm0, 2));
        cm1 = fmaxf(cm1, __shfl_xor_sync(0xffffffffu, cm1, 1));
        cm1 = fmaxf(cm1, __shfl_xor_sync(0xffffffffu, cm1, 2));

        const float mn0 = fmaxf(m0r, cm0);
        const float mn1 = fmaxf(m1r, cm1);
        const float f0 = exp2f(m0r - mn0);
        const float f1 = exp2f(m1r - mn1);

        float cs0 = 0.f, cs1 = 0.f;
#pragma unroll
        for (int nt = 0; nt < 8; nt++) {
            sacc[nt][0] = exp2f(sacc[nt][0] - mn0);
            sacc[nt][1] = exp2f(sacc[nt][1] - mn0);
            sacc[nt][2] = exp2f(sacc[nt][2] - mn1);
            sacc[nt][3] = exp2f(sacc[nt][3] - mn1);
            cs0 += sacc[nt][0] + sacc[nt][1];
            cs1 += sacc[nt][2] + sacc[nt][3];
        }
        cs0 += __shfl_xor_sync(0xffffffffu, cs0, 1);
        cs0 += __shfl_xor_sync(0xffffffffu, cs0, 2);
        cs1 += __shfl_xor_sync(0xffffffffu, cs1, 1);
        cs1 += __shfl_xor_sync(0xffffffffu, cs1, 2);

        l0r = l0r * f0 + cs0;  m0r = mn0;
        l1r = l1r * f1 + cs1;  m1r = mn1;
#pragma unroll
        for (int dt = 0; dt < 8; dt++) {
            yacc[dt][0] *= f0; yacc[dt][1] *= f0;
            yacc[dt][2] *= f1; yacc[dt][3] *= f1;
        }

        // Y += P V  (P hi-only -> 1 MMA per tile)
#pragma unroll
        for (int ks = 0; ks < 4; ks++) {
            unsigned a0 = pack_h2(sacc[2 * ks][0],     sacc[2 * ks][1]);
            unsigned a1 = pack_h2(sacc[2 * ks][2],     sacc[2 * ks][3]);
            unsigned a2 = pack_h2(sacc[2 * ks + 1][0], sacc[2 * ks + 1][1]);
            unsigned a3 = pack_h2(sacc[2 * ks + 1][2], sacc[2 * ks + 1][3]);
            const int kwa = 8 * ks + tig;
#pragma unroll
            for (int dt = 0; dt < 8; dt++) {
                const int cc = 8 * dt + g;
                mma_f16(yacc[dt], a0, a1, a2, a3,
                        sV[kwa * AK2 + (cc ^ t8)],
                        sV[(kwa + 4) * AK2 + (cc ^ t8)]);
            }
        }
        __syncthreads();
    }

    const float inv0 = 1.0f / l0r;
    const float inv1 = 1.0f / l1r;
    const size_t r0 = (size_t)(b * T_DIM + t0 + wm + g);
#pragma unroll
    for (int dt = 0; dt < 8; dt++) {
        const int col = 8 * dt + 2 * tig;
        const int cw  = h * 32 + (col >> 1);
        ys[r0 * 512 + cw]       = splitw(yacc[dt][0] * inv0, yacc[dt][1] * inv0);
        ys[(r0 + 8) * 512 + cw] = splitw(yacc[dt][2] * inv1, yacc[dt][3] * inv1);
    }
}

// ---------------------------------------------------------------------------
// Launch
// ---------------------------------------------------------------------------
extern "C" void kernel_launch(void* const* d_in, const int* in_sizes, int n_in,
                              void* d_out, int out_size)
{
    const float* x   = (const float*)d_in[0];
    const float* enc = (const float*)d_in[1];
    const float* Wq  = (const float*)d_in[2];
    const float* bq  = (const float*)d_in[3];
    const float* Wkv = (const float*)d_in[4];
    const float* bkv = (const float*)d_in[5];
    const float* Wo  = (const float*)d_in[6];
    const float* bo  = (const float*)d_in[7];
    float* out = (float*)d_out;

    uint2 *xs, *es, *qsp, *ysp;
    unsigned *wqh, *wkvh, *woh, *kvh;
    cudaGetSymbolAddress((void**)&xs,   g_xs);
    cudaGetSymbolAddress((void**)&es,   g_es);
    cudaGetSymbolAddress((void**)&wqh,  g_wqh);
    cudaGetSymbolAddress((void**)&wkvh, g_wkvh);
    cudaGetSymbolAddress((void**)&woh,  g_woh);
    cudaGetSymbolAddress((void**)&qsp,  g_qs);
    cudaGetSymbolAddress((void**)&kvh,  g_kvh);
    cudaGetSymbolAddress((void**)&ysp,  g_ys);

    cudaFuncSetAttribute(attn_flash,
                         cudaFuncAttributeMaxDynamicSharedMemorySize, ATTN_BYTES);

    // conversions
    {
        int n;
        n = BATCH * T_DIM * C_DIM / 2;
        convert_split<<<(n + 255) / 256, 256>>>((const float2*)x, xs, n);
        n = BATCH * I_DIM * C_DIM / 2;
        convert_split<<<(n + 255) / 256, 256>>>((const float2*)enc, es, n);
        n = C_DIM * C_DIM / 2;
        convert_hi<<<(n + 255) / 256, 256>>>((const float2*)Wq, wqh, n);
        n = 2 * C_DIM * C_DIM / 2;
        convert_hi<<<(n + 255) / 256, 256>>>((const float2*)Wkv, wkvh, n);
        n = C_DIM * C_DIM / 2;
        convert_hi<<<(n + 255) / 256, 256>>>((const float2*)Wo, woh, n);
    }

    // Q = x Wq^T + bq  -> split q
    gemm_split<1><<<dim3(C_DIM / 128, BATCH * T_DIM / 128), 256>>>(
        xs, wqh, bq, nullptr, qsp, nullptr, BATCH * T_DIM, C_DIM, C_DIM / 2);

    // KV = enc Wkv^T + bkv -> hi-only kv plane
    gemm_split<2><<<dim3(2 * C_DIM / 128, BATCH * I_DIM / 128), 256>>>(
        es, wkvh, bkv, nullptr, nullptr, kvh, BATCH * I_DIM, 2 * C_DIM, C_DIM / 2);

    // flash attention -> split y
    attn_flash<<<dim3(T_DIM / 128, N_HEAD, BATCH), 256, ATTN_BYTES>>>(
        qsp, kvh, ysp);

    // out = y Wo^T + bo  (fp32)
    gemm_split<0><<<dim3(C_DIM / 128, BATCH * T_DIM / 128), 256>>>(
        ysp, woh, bo, out, nullptr, nullptr, BATCH * T_DIM, C_DIM, C_DIM / 2);
}

// round 17
// speedup vs baseline: 1.5754x; 1.0253x over previous
#include <cuda_runtime.h>
#include <cuda_bf16.h>
#include <cuda_fp16.h>
#include <math.h>

// Problem constants
#define BATCH  8
#define T_DIM  1024
#define I_DIM  576
#define C_DIM  1024
#define N_HEAD 16
#define HD     64

// ---------------------------------------------------------------------------
// Scratch planes.
// Split plane (A operands): uint2 = (f16x2 hi, f16x2 lo), pairs along last dim.
// Hi plane (B operands):    unsigned = f16x2 hi, pairs along last dim.
// ---------------------------------------------------------------------------
__device__ uint2    g_xs  [BATCH * T_DIM * C_DIM / 2];
__device__ uint2    g_es  [BATCH * I_DIM * C_DIM / 2];
__device__ unsigned g_wqh [C_DIM * C_DIM / 2];
__device__ unsigned g_wkvh[2 * C_DIM * C_DIM / 2];
__device__ unsigned g_woh [C_DIM * C_DIM / 2];
__device__ uint2    g_qs  [BATCH * T_DIM * C_DIM / 2];
__device__ unsigned g_kvh [BATCH * I_DIM * 2 * C_DIM / 2];
__device__ uint2    g_ys  [BATCH * T_DIM * C_DIM / 2];

// ---------------------------------------------------------------------------
// helpers (fp16 2-term split)
// ---------------------------------------------------------------------------
__device__ __forceinline__ unsigned pack_h2(float x, float y) {
    __half2 t = __floats2half2_rn(x, y);
    return *reinterpret_cast<unsigned*>(&t);
}
__device__ __forceinline__ uint2 splitw(float x, float y) {
    float hx = __half2float(__float2half(x));
    float hy = __half2float(__float2half(y));
    return make_uint2(pack_h2(hx, hy), pack_h2(x - hx, y - hy));
}
__device__ __forceinline__ unsigned prmt(unsigned a, unsigned b, unsigned s) {
    unsigned d;
    asm("prmt.b32 %0,%1,%2,%3;" : "=r"(d) : "r"(a), "r"(b), "r"(s));
    return d;
}
__device__ __forceinline__ void mma_f16(float* c,
    unsigned a0, unsigned a1, unsigned a2, unsigned a3,
    unsigned b0, unsigned b1)
{
    asm volatile(
        "mma.sync.aligned.m16n8k16.row.col.f32.f16.f16.f32 "
        "{%0,%1,%2,%3},{%4,%5,%6,%7},{%8,%9},{%0,%1,%2,%3};\n"
        : "+f"(c[0]), "+f"(c[1]), "+f"(c[2]), "+f"(c[3])
        : "r"(a0), "r"(a1), "r"(a2), "r"(a3), "r"(b0), "r"(b1));
}
// 2-term split product: (ah + al) * bh
__device__ __forceinline__ void mma_split2(float* c, const uint2 a[4],
                                           unsigned b0, unsigned b1) {
    mma_f16(c, a[0].x, a[1].x, a[2].x, a[3].x, b0, b1);
    mma_f16(c, a[0].y, a[1].y, a[2].y, a[3].y, b0, b1);
}

// ---------------------------------------------------------------------------
// conversions: fp32 -> split plane / hi plane
// ---------------------------------------------------------------------------
__global__ __launch_bounds__(256) void convert_split(
    const float2* __restrict__ src, uint2* __restrict__ dst, int n)
{
    int i = blockIdx.x * 256 + threadIdx.x;
    if (i < n) { float2 v = src[i]; dst[i] = splitw(v.x, v.y); }
}
__global__ __launch_bounds__(256) void convert_hi(
    const float2* __restrict__ src, unsigned* __restrict__ dst, int n)
{
    int i = blockIdx.x * 256 + threadIdx.x;
    if (i < n) { float2 v = src[i]; dst[i] = pack_h2(v.x, v.y); }
}

// ---------------------------------------------------------------------------
// GEMM NT: C[M,N] = A[M,K] B[N,K]^T + bias.  A = split plane, B = hi plane.
// Block 128x128, stage = k16 (8 words), double-buffered. 8 warps (4m x 2n),
// warp tile 32x64. OUT: 0 = fp32, 1 = split uint2, 2 = hi unsigned.
// (unchanged from R16)
// ---------------------------------------------------------------------------
#define MS2 132
__device__ __forceinline__ int sidx(int kw, int m) {
    return kw * MS2 + (m ^ ((kw & 3) << 3));
}
#define STG (8 * MS2)

template<int OUT>
__global__ __launch_bounds__(256) void gemm_split(
    const uint2* __restrict__ AS, const unsigned* __restrict__ BH,
    const float* __restrict__ bias, float* __restrict__ Cf,
    uint2* __restrict__ Cs, unsigned* __restrict__ Ch, int M, int N, int KW)
{
    __shared__ uint2    sA[2 * STG];
    __shared__ unsigned sB[2 * STG];

    const int tid  = threadIdx.x;
    const int m0   = blockIdx.y * 128;
    const int n0   = blockIdx.x * 128;
    const int wid  = tid >> 5;
    const int lane = tid & 31;
    const int g    = lane >> 2;
    const int tig  = lane & 3;
    const int t8   = tig << 3;
    const int wm   = (wid >> 1) * 32;   // 4 m-groups
    const int wn   = (wid & 1) * 64;    // 2 n-groups

    const int lr = tid >> 1;          // 0..127
    const int jb = (tid & 1) * 4;     // word offset 0 or 4

    const uint4* Ag = (const uint4*)(AS + (size_t)(m0 + lr) * KW + jb);
    const uint4* Bg = (const uint4*)(BH + (size_t)(n0 + lr) * KW + jb);

    float acc[2][8][4];
#pragma unroll
    for (int i = 0; i < 2; i++)
#pragma unroll
        for (int j = 0; j < 8; j++)
#pragma unroll
            for (int r = 0; r < 4; r++) acc[i][j][r] = 0.f;

    const int NS = KW >> 3;
    uint4 a0, a1, b0;

    a0 = Ag[0]; a1 = Ag[1]; b0 = Bg[0];
    {
        sA[sidx(jb + 0, lr)] = make_uint2(a0.x, a0.y);
        sA[sidx(jb + 1, lr)] = make_uint2(a0.z, a0.w);
        sA[sidx(jb + 2, lr)] = make_uint2(a1.x, a1.y);
        sA[sidx(jb + 3, lr)] = make_uint2(a1.z, a1.w);
        sB[sidx(jb + 0, lr)] = b0.x;
        sB[sidx(jb + 1, lr)] = b0.y;
        sB[sidx(jb + 2, lr)] = b0.z;
        sB[sidx(jb + 3, lr)] = b0.w;
    }
    __syncthreads();

    for (int s = 0; s < NS; s++) {
        const int cur = s & 1;
        if (s + 1 < NS) {
            const uint4* ap = Ag + (size_t)(s + 1) * 4;
            a0 = ap[0]; a1 = ap[1];
            b0 = Bg[(size_t)(s + 1) * 2];
        }

        const uint2*    sa = sA + cur * STG;
        const unsigned* sb = sB + cur * STG;

        uint2 af[2][4];
#pragma unroll
        for (int mt = 0; mt < 2; mt++) {
            const int r = wm + 16 * mt + g;
            af[mt][0] = sa[tig * MS2 + (r ^ t8)];
            af[mt][1] = sa[tig * MS2 + ((r + 8) ^ t8)];
            af[mt][2] = sa[(tig + 4) * MS2 + (r ^ t8)];
            af[mt][3] = sa[(tig + 4) * MS2 + ((r + 8) ^ t8)];
        }
        unsigned bf[8][2];
#pragma unroll
        for (int nt = 0; nt < 8; nt++) {
            const int c = wn + 8 * nt + g;
            bf[nt][0] = sb[tig * MS2 + (c ^ t8)];
            bf[nt][1] = sb[(tig + 4) * MS2 + (c ^ t8)];
        }
#pragma unroll
        for (int mt = 0; mt < 2; mt++)
#pragma unroll
            for (int nt = 0; nt < 8; nt++)
                mma_split2(acc[mt][nt], af[mt], bf[nt][0], bf[nt][1]);

        if (s + 1 < NS) {
            uint2*    dA = sA + ((s + 1) & 1) * STG;
            unsigned* dB = sB + ((s + 1) & 1) * STG;
            dA[sidx(jb + 0, lr)] = make_uint2(a0.x, a0.y);
            dA[sidx(jb + 1, lr)] = make_uint2(a0.z, a0.w);
            dA[sidx(jb + 2, lr)] = make_uint2(a1.x, a1.y);
            dA[sidx(jb + 3, lr)] = make_uint2(a1.z, a1.w);
            dB[sidx(jb + 0, lr)] = b0.x;
            dB[sidx(jb + 1, lr)] = b0.y;
            dB[sidx(jb + 2, lr)] = b0.z;
            dB[sidx(jb + 3, lr)] = b0.w;
        }
        __syncthreads();
    }

#pragma unroll
    for (int mt = 0; mt < 2; mt++) {
        const int r0 = m0 + wm + 16 * mt + g;
#pragma unroll
        for (int nt = 0; nt < 8; nt++) {
            const int cb = n0 + wn + 8 * nt + 2 * tig;
            const float v0 = bias[cb], v1 = bias[cb + 1];
            const float c0 = acc[mt][nt][0] + v0, c1 = acc[mt][nt][1] + v1;
            const float c2 = acc[mt][nt][2] + v0, c3 = acc[mt][nt][3] + v1;
            if (OUT == 1) {
                Cs[(size_t)r0 * (N >> 1) + (cb >> 1)]       = splitw(c0, c1);
                Cs[(size_t)(r0 + 8) * (N >> 1) + (cb >> 1)] = splitw(c2, c3);
            } else if (OUT == 2) {
                Ch[(size_t)r0 * (N >> 1) + (cb >> 1)]       = pack_h2(c0, c1);
                Ch[(size_t)(r0 + 8) * (N >> 1) + (cb >> 1)] = pack_h2(c2, c3);
            } else {
                *(float2*)(Cf + (size_t)r0 * N + cb)       = make_float2(c0, c1);
                *(float2*)(Cf + (size_t)(r0 + 8) * N + cb) = make_float2(c2, c3);
            }
        }
    }
}

// ---------------------------------------------------------------------------
// Flash attention, software-pipelined chunk loop.
// Q split (A); K/V hi plane (B); P hi-only. Double-buffered sK/sV:
// prefetch next chunk into regs (uint2 LDGs) during compute, store to the
// alternate buffer, ONE __syncthreads per chunk.
// ---------------------------------------------------------------------------
#define AQ2 136   // sQ stride (uint2)
#define AK2 68    // sK/sV stride (unsigned)
#define AKB (32 * AK2)                               // words per K/V buffer
#define ATTN_BYTES (32 * AQ2 * 8 + 4 * AKB * 4)      // ~68 KB
#define SCALE_L2E 0.1803368801111204f   // 0.125 * log2(e)
#define NCHUNK 9

__global__ __launch_bounds__(256) void attn_flash(
    const uint2* __restrict__ qs, const unsigned* __restrict__ kvh,
    uint2* __restrict__ ys)
{
    extern __shared__ char smraw[];
    uint2*    sQ  = (uint2*)smraw;                         // [32 kw][128 r]
    unsigned* sKb = (unsigned*)(smraw + 32 * AQ2 * 8);     // [2][32][64]
    unsigned* sVb = sKb + 2 * AKB;                         // [2][32][64]

    const int tid  = threadIdx.x;
    const int wid  = tid >> 5;
    const int lane = tid & 31;
    const int g    = lane >> 2;
    const int tig  = lane & 3;
    const int t8   = tig << 3;
    const int wm   = wid * 16;

    const int b  = blockIdx.z;
    const int h  = blockIdx.y;
    const int t0 = blockIdx.x * 128;

    // prefetch thread mapping
    const int kr  = tid >> 4;          // K: row 0..15 (x2 passes), dw pair
    const int kd2 = tid & 15;          // K: uint2 index along dw (dw = 2*kd2)
    const int vi  = tid >> 4;          // V: iw 0..15 (x2 passes)
    const int vd2 = tid & 15;          // V: uint2 index along dv

    const size_t kvbase = (size_t)(b * I_DIM) * 1024 + h * 32;

    // Q tile load
#pragma unroll
    for (int w = 0; w < 16; w++) {
        int idx = tid + 256 * w;
        int r = idx >> 5, dw = idx & 31;
        sQ[dw * AQ2 + (r ^ ((dw & 3) << 3))] =
            qs[(size_t)(b * T_DIM + t0 + r) * 512 + h * 32 + dw];
    }

    uint2 kpf[4];        // K prefetch: rows kr, kr+16, kr+32, kr+48 @ dw pair kd2
    uint2 vpfA[2], vpfB[2];  // V prefetch: iw vi, vi+16 @ dv pair vd2, rows 2iw/2iw+1

    // helper lambdas (macros to keep regs tight)
#define PREFETCH_CHUNK(i0)                                                      \
    {                                                                           \
        const unsigned* kb = kvh + kvbase + (size_t)(i0) * 1024;                \
        kpf[0] = *(const uint2*)(kb + (size_t)(kr)      * 1024 + 2 * kd2);      \
        kpf[1] = *(const uint2*)(kb + (size_t)(kr + 16) * 1024 + 2 * kd2);      \
        kpf[2] = *(const uint2*)(kb + (size_t)(kr + 32) * 1024 + 2 * kd2);      \
        kpf[3] = *(const uint2*)(kb + (size_t)(kr + 48) * 1024 + 2 * kd2);      \
        const unsigned* vb = kb + 512;                                          \
        vpfA[0] = *(const uint2*)(vb + (size_t)(2 * vi)      * 1024 + 2 * vd2); \
        vpfA[1] = *(const uint2*)(vb + (size_t)(2 * vi + 1)  * 1024 + 2 * vd2); \
        vpfB[0] = *(const uint2*)(vb + (size_t)(2 * (vi+16))     * 1024 + 2 * vd2); \
        vpfB[1] = *(const uint2*)(vb + (size_t)(2 * (vi+16) + 1) * 1024 + 2 * vd2); \
    }

#define STORE_CHUNK(buf)                                                        \
    {                                                                           \
        unsigned* dk = sKb + (buf) * AKB;                                       \
        const int dw0 = 2 * kd2, dw1 = 2 * kd2 + 1;                             \
        dk[dw0 * AK2 + ((kr)      ^ ((dw0 & 3) << 3))] = kpf[0].x;              \
        dk[dw1 * AK2 + ((kr)      ^ ((dw1 & 3) << 3))] = kpf[0].y;              \
        dk[dw0 * AK2 + ((kr + 16) ^ ((dw0 & 3) << 3))] = kpf[1].x;              \
        dk[dw1 * AK2 + ((kr + 16) ^ ((dw1 & 3) << 3))] = kpf[1].y;              \
        dk[dw0 * AK2 + ((kr + 32) ^ ((dw0 & 3) << 3))] = kpf[2].x;              \
        dk[dw1 * AK2 + ((kr + 32) ^ ((dw1 & 3) << 3))] = kpf[2].y;              \
        dk[dw0 * AK2 + ((kr + 48) ^ ((dw0 & 3) << 3))] = kpf[3].x;              \
        dk[dw1 * AK2 + ((kr + 48) ^ ((dw1 & 3) << 3))] = kpf[3].y;              \
        unsigned* dv = sVb + (buf) * AKB;                                       \
        {                                                                       \
            const int iw = vi, c0 = 4 * vd2, sw = (iw & 3) << 3;                \
            dv[iw * AK2 + ((c0    ) ^ sw)] = prmt(vpfA[0].x, vpfA[1].x, 0x5410);\
            dv[iw * AK2 + ((c0 + 1) ^ sw)] = prmt(vpfA[0].x, vpfA[1].x, 0x7632);\
            dv[iw * AK2 + ((c0 + 2) ^ sw)] = prmt(vpfA[0].y, vpfA[1].y, 0x5410);\
            dv[iw * AK2 + ((c0 + 3) ^ sw)] = prmt(vpfA[0].y, vpfA[1].y, 0x7632);\
        }                                                                       \
        {                                                                       \
            const int iw = vi + 16, c0 = 4 * vd2, sw = (iw & 3) << 3;           \
            dv[iw * AK2 + ((c0    ) ^ sw)] = prmt(vpfB[0].x, vpfB[1].x, 0x5410);\
            dv[iw * AK2 + ((c0 + 1) ^ sw)] = prmt(vpfB[0].x, vpfB[1].x, 0x7632);\
            dv[iw * AK2 + ((c0 + 2) ^ sw)] = prmt(vpfB[0].y, vpfB[1].y, 0x5410);\
            dv[iw * AK2 + ((c0 + 3) ^ sw)] = prmt(vpfB[0].y, vpfB[1].y, 0x7632);\
        }                                                                       \
    }

    // prologue: chunk 0
    PREFETCH_CHUNK(0);
    STORE_CHUNK(0);

    float yacc[8][4];
#pragma unroll
    for (int dt = 0; dt < 8; dt++)
#pragma unroll
        for (int r = 0; r < 4; r++) yacc[dt][r] = 0.f;
    float m0r = -1e30f, m1r = -1e30f;
    float l0r = 0.f, l1r = 0.f;

    __syncthreads();

    for (int c = 0; c < NCHUNK; c++) {
        const int cur = c & 1;
        if (c + 1 < NCHUNK) PREFETCH_CHUNK((c + 1) * 64);

        const unsigned* sK = sKb + cur * AKB;
        const unsigned* sV = sVb + cur * AKB;

        // S = Q K^T
        float sacc[8][4];
#pragma unroll
        for (int nt = 0; nt < 8; nt++)
#pragma unroll
            for (int r = 0; r < 4; r++) sacc[nt][r] = 0.f;

#pragma unroll
        for (int ks = 0; ks < 4; ks++) {
            const int kwa = 8 * ks + tig;
            uint2 af[4];
            af[0] = sQ[kwa * AQ2 + ((wm + g) ^ t8)];
            af[1] = sQ[kwa * AQ2 + ((wm + g + 8) ^ t8)];
            af[2] = sQ[(kwa + 4) * AQ2 + ((wm + g) ^ t8)];
            af[3] = sQ[(kwa + 4) * AQ2 + ((wm + g + 8) ^ t8)];
#pragma unroll
            for (int nt = 0; nt < 8; nt++) {
                const int cc = 8 * nt + g;
                mma_split2(sacc[nt], af,
                           sK[kwa * AK2 + (cc ^ t8)],
                           sK[(kwa + 4) * AK2 + (cc ^ t8)]);
            }
        }

        // online softmax (log2 domain)
        float cm0 = -1e30f, cm1 = -1e30f;
#pragma unroll
        for (int nt = 0; nt < 8; nt++) {
            sacc[nt][0] *= SCALE_L2E; sacc[nt][1] *= SCALE_L2E;
            sacc[nt][2] *= SCALE_L2E; sacc[nt][3] *= SCALE_L2E;
            cm0 = fmaxf(cm0, fmaxf(sacc[nt][0], sacc[nt][1]));
            cm1 = fmaxf(cm1, fmaxf(sacc[nt][2], sacc[nt][3]));
        }
        cm0 = fmaxf(cm0, __shfl_xor_sync(0xffffffffu, cm0, 1));
        cm0 = fmaxf(cm0, __shfl_xor_sync(0xffffffffu, cm0, 2));
        cm1 = fmaxf(cm1, __shfl_xor_sync(0xffffffffu, cm1, 1));
        cm1 = fmaxf(cm1, __shfl_xor_sync(0xffffffffu, cm1, 2));

        const float mn0 = fmaxf(m0r, cm0);
        const float mn1 = fmaxf(m1r, cm1);
        const float f0 = exp2f(m0r - mn0);
        const float f1 = exp2f(m1r - mn1);

        float cs0 = 0.f, cs1 = 0.f;
#pragma unroll
        for (int nt = 0; nt < 8; nt++) {
            sacc[nt][0] = exp2f(sacc[nt][0] - mn0);
            sacc[nt][1] = exp2f(sacc[nt][1] - mn0);
            sacc[nt][2] = exp2f(sacc[nt][2] - mn1);
            sacc[nt][3] = exp2f(sacc[nt][3] - mn1);
            cs0 += sacc[nt][0] + sacc[nt][1];
            cs1 += sacc[nt][2] + sacc[nt][3];
        }
        cs0 += __shfl_xor_sync(0xffffffffu, cs0, 1);
        cs0 += __shfl_xor_sync(0xffffffffu, cs0, 2);
        cs1 += __shfl_xor_sync(0xffffffffu, cs1, 1);
        cs1 += __shfl_xor_sync(0xffffffffu, cs1, 2);

        l0r = l0r * f0 + cs0;  m0r = mn0;
        l1r = l1r * f1 + cs1;  m1r = mn1;
#pragma unroll
        for (int dt = 0; dt < 8; dt++) {
            yacc[dt][0] *= f0; yacc[dt][1] *= f0;
            yacc[dt][2] *= f1; yacc[dt][3] *= f1;
        }

        // Y += P V  (P hi-only)
#pragma unroll
        for (int ks = 0; ks < 4; ks++) {
            unsigned a0 = pack_h2(sacc[2 * ks][0],     sacc[2 * ks][1]);
            unsigned a1 = pack_h2(sacc[2 * ks][2],     sacc[2 * ks][3]);
            unsigned a2 = pack_h2(sacc[2 * ks + 1][0], sacc[2 * ks + 1][1]);
            unsigned a3 = pack_h2(sacc[2 * ks + 1][2], sacc[2 * ks + 1][3]);
            const int kwa = 8 * ks + tig;
#pragma unroll
            for (int dt = 0; dt < 8; dt++) {
                const int cc = 8 * dt + g;
                mma_f16(yacc[dt], a0, a1, a2, a3,
                        sV[kwa * AK2 + (cc ^ t8)],
                        sV[(kwa + 4) * AK2 + (cc ^ t8)]);
            }
        }

        if (c + 1 < NCHUNK) STORE_CHUNK((c + 1) & 1);
        __syncthreads();
    }

    const float inv0 = 1.0f / l0r;
    const float inv1 = 1.0f / l1r;
    const size_t r0 = (size_t)(b * T_DIM + t0 + wm + g);
#pragma unroll
    for (int dt = 0; dt < 8; dt++) {
        const int col = 8 * dt + 2 * tig;
        const int cw  = h * 32 + (col >> 1);
        ys[r0 * 512 + cw]       = splitw(yacc[dt][0] * inv0, yacc[dt][1] * inv0);
        ys[(r0 + 8) * 512 + cw] = splitw(yacc[dt][2] * inv1, yacc[dt][3] * inv1);
    }
}

// ---------------------------------------------------------------------------
// Launch
// ---------------------------------------------------------------------------
extern "C" void kernel_launch(void* const* d_in, const int* in_sizes, int n_in,
                              void* d_out, int out_size)
{
    const float* x   = (const float*)d_in[0];
    const float* enc = (const float*)d_in[1];
    const float* Wq  = (const float*)d_in[2];
    const float* bq  = (const float*)d_in[3];
    const float* Wkv = (const float*)d_in[4];
    const float* bkv = (const float*)d_in[5];
    const float* Wo  = (const float*)d_in[6];
    const float* bo  = (const float*)d_in[7];
    float* out = (float*)d_out;

    uint2 *xs, *es, *qsp, *ysp;
    unsigned *wqh, *wkvh, *woh, *kvh;
    cudaGetSymbolAddress((void**)&xs,   g_xs);
    cudaGetSymbolAddress((void**)&es,   g_es);
    cudaGetSymbolAddress((void**)&wqh,  g_wqh);
    cudaGetSymbolAddress((void**)&wkvh, g_wkvh);
    cudaGetSymbolAddress((void**)&woh,  g_woh);
    cudaGetSymbolAddress((void**)&qsp,  g_qs);
    cudaGetSymbolAddress((void**)&kvh,  g_kvh);
    cudaGetSymbolAddress((void**)&ysp,  g_ys);

    cudaFuncSetAttribute(attn_flash,
                         cudaFuncAttributeMaxDynamicSharedMemorySize, ATTN_BYTES);

    // conversions
    {
        int n;
        n = BATCH * T_DIM * C_DIM / 2;
        convert_split<<<(n + 255) / 256, 256>>>((const float2*)x, xs, n);
        n = BATCH * I_DIM * C_DIM / 2;
        convert_split<<<(n + 255) / 256, 256>>>((const float2*)enc, es, n);
        n = C_DIM * C_DIM / 2;
        convert_hi<<<(n + 255) / 256, 256>>>((const float2*)Wq, wqh, n);
        n = 2 * C_DIM * C_DIM / 2;
        convert_hi<<<(n + 255) / 256, 256>>>((const float2*)Wkv, wkvh, n);
        n = C_DIM * C_DIM / 2;
        convert_hi<<<(n + 255) / 256, 256>>>((const float2*)Wo, woh, n);
    }

    // Q = x Wq^T + bq  -> split q
    gemm_split<1><<<dim3(C_DIM / 128, BATCH * T_DIM / 128), 256>>>(
        xs, wqh, bq, nullptr, qsp, nullptr, BATCH * T_DIM, C_DIM, C_DIM / 2);

    // KV = enc Wkv^T + bkv -> hi-only kv plane
    gemm_split<2><<<dim3(2 * C_DIM / 128, BATCH * I_DIM / 128), 256>>>(
        es, wkvh, bkv, nullptr, nullptr, kvh, BATCH * I_DIM, 2 * C_DIM, C_DIM / 2);

    // flash attention -> split y
    attn_flash<<<dim3(T_DIM / 128, N_HEAD, BATCH), 256, ATTN_BYTES>>>(
        qsp, kvh, ysp);

    // out = y Wo^T + bo  (fp32)
    gemm_split<0><<<dim3(C_DIM / 128, BATCH * T_DIM / 128), 256>>>(
        ysp, woh, bo, out, nullptr, nullptr, BATCH * T_DIM, C_DIM, C_DIM / 2);
}